// round 11
// baseline (speedup 1.0000x reference)
#include <cuda_runtime.h>
#include <cuda_bf16.h>
#include <cstdint>

constexpr int Bb  = 64;
constexpr int BSs = 8;
constexpr int Mm  = 512;
constexpr int Dd  = 256;
constexpr float NEG_FILL_F = -10000000000.0f;

// bf16 fused path: chunk = 32 bf16 k; stage = 4 tiles (Ahi,Alo,Bhi,Blo) x 8KB
constexpr int DEPTH_BF = 2;
constexpr int TSZ     = 8192;                          // bytes per tile
constexpr int BSTAGE  = 4 * TSZ;                       // 32KB per stage
constexpr int DSMEM_BF = DEPTH_BF * BSTAGE;            // 65536 B -> 3 CTAs/SM
// fp32 NN path (ctx): BK=16 fp32
constexpr int DEPTH_NN = 3;
constexpr int BK32   = 16;
constexpr int BNNP   = 136;
constexpr int ASTG32   = 128 * BK32;                   // floats
constexpr int BSTG_NN  = BK32 * BNNP;                  // floats
constexpr int DSMEM_NN = DEPTH_NN * (ASTG32 + BSTG_NN) * 4;  // 50688 B -> 3 CTAs/SM

// ---------------- scratch ------------------------------------------------------
__device__ __nv_bfloat16 g_x2[(size_t)Bb * Mm * 2 * Dd];   // [hi|lo] width 512
__device__ __nv_bfloat16 g_y2[(size_t)BSs * Mm * 2 * Dd];
__device__ __nv_bfloat16 g_W2[3][(size_t)Dd * 2 * Dd];
__device__ __nv_bfloat16 g_Qx2[(size_t)Bb * Mm * 2 * Dd];
__device__ __nv_bfloat16 g_Kx2[(size_t)Bb * Mm * 2 * Dd];
__device__ __nv_bfloat16 g_Qy2[(size_t)BSs * Mm * 2 * Dd];
__device__ __nv_bfloat16 g_Ky2[(size_t)BSs * Mm * 2 * Dd];
__device__ float g_Vx[(size_t)Bb * Mm * Dd];        // V fp32 tf32-rna
__device__ float g_Vy[(size_t)BSs * Mm * Dd];
__device__ float g_Px[(size_t)Bb * Mm * Mm];        // probs tf32-rna, sp-permuted
__device__ float g_Py[(size_t)BSs * Mm * Mm];
__device__ unsigned char g_mx[Bb * Mm];
__device__ unsigned char g_my[BSs * Mm];

// ---------------- helpers ------------------------------------------------------
__device__ __forceinline__ int sp(int k) {          // involution, used for P only
    return (k & ~15) | ((k & 3) << 2) | ((k >> 2) & 3);
}
__device__ __forceinline__ float tf32_rna(float a) {
    uint32_t o;
    asm("cvt.rna.tf32.f32 %0, %1;" : "=r"(o) : "f"(a));
    return __uint_as_float(o);
}
__device__ __forceinline__ uint32_t smem_u32(const void* p) {
    uint32_t a;
    asm("{ .reg .u64 t; cvta.to.shared.u64 t, %1; cvt.u32.u64 %0, t; }"
        : "=r"(a) : "l"(p));
    return a;
}
__device__ __forceinline__ void cpa16(uint32_t dst, const void* src) {
    asm volatile("cp.async.cg.shared.global [%0], [%1], 16;"
                 :: "r"(dst), "l"(src) : "memory");
}
__device__ __forceinline__ void ldm_x4(uint32_t* r, uint32_t addr) {
    asm volatile("ldmatrix.sync.aligned.m8n8.x4.shared.b16 {%0,%1,%2,%3}, [%4];"
        : "=r"(r[0]), "=r"(r[1]), "=r"(r[2]), "=r"(r[3]) : "r"(addr));
}
__device__ __forceinline__ void mma_bf16(float* c, const uint32_t* a,
                                         uint32_t b0, uint32_t b1) {
    asm volatile(
        "mma.sync.aligned.m16n8k16.row.col.f32.bf16.bf16.f32 "
        "{%0,%1,%2,%3}, {%4,%5,%6,%7}, {%8,%9}, {%0,%1,%2,%3};"
        : "+f"(c[0]), "+f"(c[1]), "+f"(c[2]), "+f"(c[3])
        : "r"(a[0]), "r"(a[1]), "r"(a[2]), "r"(a[3]), "r"(b0), "r"(b1));
}
__device__ __forceinline__ void mma_tf32(float* c, const uint32_t* a, const uint32_t* b) {
    asm volatile(
        "mma.sync.aligned.m16n8k8.row.col.f32.tf32.tf32.f32 "
        "{%0,%1,%2,%3}, {%4,%5,%6,%7}, {%8,%9}, {%0,%1,%2,%3};"
        : "+f"(c[0]), "+f"(c[1]), "+f"(c[2]), "+f"(c[3])
        : "r"(a[0]), "r"(a[1]), "r"(a[2]), "r"(a[3]), "r"(b[0]), "r"(b[1]));
}

// ============================ fused bf16 NT GEMM path ==========================
// Per 32-k chunk, stage 4 tiles (Ahi,Alo,Bhi,Blo), each 128 rows x 64B.
// Slot swizzle (4 slots of 16B / row): phys_slot = g ^ ((row>>1)&3).
// One chunk issues all three product terms hi*hi + lo*hi + hi*lo.
__device__ __forceinline__ void issue_stage_f(
    const __nv_bfloat16* __restrict__ A, const __nv_bfloat16* __restrict__ B,
    int c, int nch, uint32_t sb)
{
    if (c < nch) {
        uint32_t sd = sb + (c % DEPTH_BF) * BSTAGE;
        int acol = c * 32;
#pragma unroll
        for (int j = 0; j < 2; j++) {
            int idx = threadIdx.x + 256 * j;
            int row = idx >> 2, slot = idx & 3;
            int g = slot ^ ((row >> 1) & 3);
            uint32_t so = row * 64 + slot * 16;
            const __nv_bfloat16* ap = A + (size_t)row * 512 + acol + g * 8;
            const __nv_bfloat16* bp = B + (size_t)row * 512 + acol + g * 8;
            cpa16(sd + so, ap);                       // A hi
            cpa16(sd + TSZ + so, ap + 256);           // A lo
            cpa16(sd + 2 * TSZ + so, bp);             // B hi
            cpa16(sd + 3 * TSZ + so, bp + 256);       // B lo
        }
    }
    asm volatile("cp.async.commit_group;" ::: "memory");
}

// warp tile 64(m) x 32(n); 8 warps 2x4 over 128x128 CTA tile; 32 k per chunk.
__device__ __forceinline__ void compute_chunk_f(
    uint32_t sd, float (&acc)[4][4][4], int wm, int wn, int lane)
{
    int j = lane >> 3, rin = lane & 7;
    int jk = j >> 1, jo = (j & 1) * 8;
    int rowA = wm * 64 + jo + rin;
    int rowB = wn * 32 + jo + rin;
    int swA = (rowA >> 1) & 3, swB = (rowB >> 1) & 3;
#pragma unroll
    for (int ks = 0; ks < 2; ks++) {
        uint32_t slA = (uint32_t)(((ks * 2 + jk) ^ swA) * 16);
        uint32_t slB = (uint32_t)(((ks * 2 + jk) ^ swB) * 16);
        uint32_t bhi[2][4], blo[2][4];
#pragma unroll
        for (int np = 0; np < 2; np++) {
            ldm_x4(bhi[np], sd + 2 * TSZ + (rowB + np * 16) * 64 + slB);
            ldm_x4(blo[np], sd + 3 * TSZ + (rowB + np * 16) * 64 + slB);
        }
#pragma unroll
        for (int mt = 0; mt < 4; mt++) {
            uint32_t ahi[4], alo[4];
            ldm_x4(ahi, sd + (rowA + mt * 16) * 64 + slA);
            ldm_x4(alo, sd + TSZ + (rowA + mt * 16) * 64 + slA);
#pragma unroll
            for (int nt = 0; nt < 4; nt++) {
                uint32_t b0 = bhi[nt >> 1][nt & 1], b1 = bhi[nt >> 1][(nt & 1) + 2];
                mma_bf16(acc[mt][nt], ahi, b0, b1);
                mma_bf16(acc[mt][nt], alo, b0, b1);
                mma_bf16(acc[mt][nt], ahi,
                         blo[nt >> 1][nt & 1], blo[nt >> 1][(nt & 1) + 2]);
            }
        }
    }
}

__device__ __forceinline__ void gemm_bf16(
    const __nv_bfloat16* __restrict__ A, const __nv_bfloat16* __restrict__ B,
    float (&acc)[4][4][4], uint32_t sb, int wm, int wn, int lane)
{
    constexpr int nch = 8;   // 8 chunks of 32 k over K=256, fused 3 terms
#pragma unroll
    for (int s = 0; s < DEPTH_BF - 1; s++)
        issue_stage_f(A, B, s, nch, sb);
    for (int c = 0; c < nch; c++) {
        asm volatile("cp.async.wait_group 0;" ::: "memory");
        __syncthreads();
        issue_stage_f(A, B, c + DEPTH_BF - 1, nch, sb);
        compute_chunk_f(sb + (c % DEPTH_BF) * BSTAGE, acc, wm, wn, lane);
    }
}

#define BF16_SETUP()                                        \
    extern __shared__ char smem[];                          \
    uint32_t sb = smem_u32(smem);                           \
    int wid = threadIdx.x >> 5, lane = threadIdx.x & 31;    \
    int wm = wid >> 2, wn = wid & 3;                        \
    int gr = lane >> 2, kc = lane & 3;                      \
    float acc[4][4][4];                                     \
    _Pragma("unroll") for (int i = 0; i < 4; i++)           \
    _Pragma("unroll") for (int jj = 0; jj < 4; jj++)        \
    _Pragma("unroll") for (int q = 0; q < 4; q++) acc[i][jj][q] = 0.f;

// ============================ fp32 NN path (ctx only) ==========================
__device__ __forceinline__ void issue_stage_nn(
    const float* __restrict__ A, int lda, const float* __restrict__ B, int ldb,
    int c, int nch, uint32_t asb, uint32_t bsb)
{
    if (c < nch) {
        int kc = c;
        int buf = c % DEPTH_NN;
        uint32_t ad = asb + buf * (ASTG32 * 4);
        uint32_t bd = bsb + buf * (BSTG_NN * 4);
#pragma unroll
        for (int j = 0; j < 2; j++) {             // A: 128 rows x 4 slots
            int idx = threadIdx.x + 256 * j;
            int row = idx >> 2, slot = idx & 3;
            int g = slot ^ (row & 3);
            cpa16(ad + row * 64 + slot * 16, A + (size_t)row * lda + kc * BK32 + g * 4);
        }
#pragma unroll
        for (int j = 0; j < 2; j++) {             // B: 16 k-rows x 32 segs
            int idx = threadIdx.x + 256 * j;
            int row = idx >> 5, seg = idx & 31;
            cpa16(bd + (row * BNNP + seg * 4) * 4,
                  B + (size_t)(kc * BK32 + row) * ldb + seg * 4);
        }
    }
    asm volatile("cp.async.commit_group;" ::: "memory");
}

__device__ __forceinline__ void compute_chunk_nn(
    const float* __restrict__ As, const float* __restrict__ Bs,
    float (&acc)[4][4][4], int wm, int wn, int gr, int kc)
{
    const int slot4 = (kc ^ (gr & 3)) * 4;
    uint32_t a[2][4][4], b[2][4][2];
#pragma unroll
    for (int mt = 0; mt < 4; mt++) {
        int r0 = wm * 64 + mt * 16 + gr;
        float4 u = *(const float4*)(As + r0 * BK32 + slot4);
        float4 w = *(const float4*)(As + (r0 + 8) * BK32 + slot4);
        a[0][mt][0] = __float_as_uint(u.x); a[0][mt][1] = __float_as_uint(w.x);
        a[0][mt][2] = __float_as_uint(u.y); a[0][mt][3] = __float_as_uint(w.y);
        a[1][mt][0] = __float_as_uint(u.z); a[1][mt][1] = __float_as_uint(w.z);
        a[1][mt][2] = __float_as_uint(u.w); a[1][mt][3] = __float_as_uint(w.w);
    }
#pragma unroll
    for (int k8 = 0; k8 < 2; k8++)
#pragma unroll
        for (int nt = 0; nt < 4; nt++) {
            const float* p = Bs + (k8 * 8 + kc) * BNNP + wn * 32 + nt * 8 + gr;
            b[k8][nt][0] = __float_as_uint(p[0]);
            b[k8][nt][1] = __float_as_uint(p[4 * BNNP]);
        }
#pragma unroll
    for (int k8 = 0; k8 < 2; k8++)
#pragma unroll
        for (int mt = 0; mt < 4; mt++)
#pragma unroll
            for (int nt = 0; nt < 4; nt++)
                mma_tf32(acc[mt][nt], a[k8][mt], b[k8][nt]);
}

// ---------------- fused split: x/y/W -> bf16 [hi | lo] --------------------------
__global__ void split_all(const float* __restrict__ x, const float* __restrict__ y,
                          const float* __restrict__ Wq, const float* __restrict__ Wk,
                          const float* __restrict__ Wv)
{
    constexpr size_t NX = (size_t)Bb * Mm * Dd;
    constexpr size_t NY = (size_t)BSs * Mm * Dd;
    constexpr size_t NW = (size_t)Dd * Dd;
    size_t i = (size_t)blockIdx.x * blockDim.x + threadIdx.x;
    if (i < NX) {
        int r = (int)(i / Dd), c = (int)(i % Dd);
        float v = x[i];
        __nv_bfloat16 h = __float2bfloat16(v);
        g_x2[(size_t)r * 512 + c] = h;
        g_x2[(size_t)r * 512 + 256 + c] = __float2bfloat16(v - __bfloat162float(h));
    } else if (i < NX + NY) {
        size_t e = i - NX;
        int r = (int)(e / Dd), c = (int)(e % Dd);
        float v = y[e];
        __nv_bfloat16 h = __float2bfloat16(v);
        g_y2[(size_t)r * 512 + c] = h;
        g_y2[(size_t)r * 512 + 256 + c] = __float2bfloat16(v - __bfloat162float(h));
    } else if (i < NX + NY + 3 * NW) {
        size_t j = i - NX - NY;
        int w = (int)(j / NW);
        size_t e = j % NW;
        int r = (int)(e / Dd), c = (int)(e % Dd);
        const float* W = (w == 0) ? Wq : (w == 1) ? Wk : Wv;
        float v = W[e];
        __nv_bfloat16 h = __float2bfloat16(v);
        g_W2[w][(size_t)r * 512 + c] = h;
        g_W2[w][(size_t)r * 512 + 256 + c] = __float2bfloat16(v - __bfloat162float(h));
    }
}

// ---------------- projections (fused 3-term bf16) -------------------------------
__global__ __launch_bounds__(256, 3) void proj_kernel()
{
    int z = blockIdx.z;
    bool isY = z >= 3;
    if (isY && blockIdx.y >= 32) return;
    int mat = z % 3;
    const __nv_bfloat16* A2 = isY ? g_y2 : g_x2;
    const __nv_bfloat16* B2 = g_W2[mat];
    int row0 = blockIdx.y * 128, col0 = blockIdx.x * 128;

    BF16_SETUP();
    gemm_bf16(A2 + (size_t)row0 * 512, B2 + (size_t)col0 * 512,
              acc, sb, wm, wn, lane);

    if (mat < 2) {
        __nv_bfloat16* Q2 = (mat == 0) ? (isY ? g_Qy2 : g_Qx2) : (isY ? g_Ky2 : g_Kx2);
#pragma unroll
        for (int mt = 0; mt < 4; mt++) {
            int r = row0 + wm * 64 + mt * 16 + gr;
#pragma unroll
            for (int nt = 0; nt < 4; nt++) {
                int c = col0 + wn * 32 + nt * 8 + kc * 2;
#pragma unroll
                for (int h2 = 0; h2 < 2; h2++) {
                    int rr = r + h2 * 8;
                    float v0 = acc[mt][nt][h2 * 2], v1 = acc[mt][nt][h2 * 2 + 1];
                    __nv_bfloat16 h0 = __float2bfloat16(v0);
                    __nv_bfloat16 h1 = __float2bfloat16(v1);
                    __nv_bfloat162 hi; hi.x = h0; hi.y = h1;
                    __nv_bfloat162 lo;
                    lo.x = __float2bfloat16(v0 - __bfloat162float(h0));
                    lo.y = __float2bfloat16(v1 - __bfloat162float(h1));
                    *(__nv_bfloat162*)(Q2 + (size_t)rr * 512 + c) = hi;
                    *(__nv_bfloat162*)(Q2 + (size_t)rr * 512 + 256 + c) = lo;
                }
            }
        }
    } else {
        float* V = isY ? g_Vy : g_Vx;
#pragma unroll
        for (int mt = 0; mt < 4; mt++) {
            int r = row0 + wm * 64 + mt * 16 + gr;
#pragma unroll
            for (int nt = 0; nt < 4; nt++) {
                int c = col0 + wn * 32 + nt * 8 + kc * 2;
#pragma unroll
                for (int h2 = 0; h2 < 2; h2++) {
                    int rr = r + h2 * 8;
                    *(float2*)(V + (size_t)rr * Dd + c) =
                        make_float2(tf32_rna(acc[mt][nt][h2 * 2]),
                                    tf32_rna(acc[mt][nt][h2 * 2 + 1]));
                }
            }
        }
    }
}

// ---------------- ALL masked score GEMMs in one launch ----------------------------
// z in [0,64): scores_x batch z; [64,128): scores_xy zb=z-64 (+ mask_xy);
// [128,136): scores_y zb=z-128.
__global__ __launch_bounds__(256, 3) void scores_all(
    float* __restrict__ sx, float* __restrict__ sy,
    float* __restrict__ pxy, float* __restrict__ mxy)
{
    int z = blockIdx.z;
    const __nv_bfloat16 *A, *Bp;
    const unsigned char *mr, *mc;
    float* C;
    float* Mx = nullptr;
    if (z < 64) {
        A = g_Qx2 + (size_t)z * Mm * 512; Bp = g_Kx2 + (size_t)z * Mm * 512;
        mr = g_mx + z * Mm; mc = mr;
        C = sx + (size_t)z * Mm * Mm;
    } else if (z < 128) {
        int zb = z - 64;
        int n = zb >> 3, s = zb & 7, b = s * 8 + n;
        A = g_Qx2 + (size_t)b * Mm * 512; Bp = g_Ky2 + (size_t)s * Mm * 512;
        mr = g_mx + b * Mm; mc = g_my + s * Mm;
        C = pxy + (size_t)zb * Mm * Mm;
        Mx = mxy + (size_t)zb * Mm * Mm;
    } else {
        int zb = z - 128;
        A = g_Qy2 + (size_t)zb * Mm * 512; Bp = g_Ky2 + (size_t)zb * Mm * 512;
        mr = g_my + zb * Mm; mc = mr;
        C = sy + (size_t)zb * Mm * Mm;
    }
    int row0 = blockIdx.y * 128, col0 = blockIdx.x * 128;

    BF16_SETUP();
    gemm_bf16(A + (size_t)row0 * 512, Bp + (size_t)col0 * 512,
              acc, sb, wm, wn, lane);

#pragma unroll
    for (int mt = 0; mt < 4; mt++) {
        int r = row0 + wm * 64 + mt * 16 + gr;
        bool rm0 = mr[r] != 0, rm1 = mr[r + 8] != 0;
#pragma unroll
        for (int nt = 0; nt < 4; nt++) {
            int c = col0 + wn * 32 + nt * 8 + kc * 2;
            bool c0 = mc[c] != 0, c1 = mc[c + 1] != 0;
            bool m00 = rm0 && c0, m01 = rm0 && c1;
            bool m10 = rm1 && c0, m11 = rm1 && c1;
            float2 v0, v1;
            v0.x = m00 ? acc[mt][nt][0] : NEG_FILL_F;
            v0.y = m01 ? acc[mt][nt][1] : NEG_FILL_F;
            v1.x = m10 ? acc[mt][nt][2] : NEG_FILL_F;
            v1.y = m11 ? acc[mt][nt][3] : NEG_FILL_F;
            *(float2*)(C + (size_t)r * Mm + c) = v0;
            *(float2*)(C + (size_t)(r + 8) * Mm + c) = v1;
            if (Mx) {
                *(float2*)(Mx + (size_t)r * Mm + c) =
                    make_float2(m00 ? 1.f : 0.f, m01 ? 1.f : 0.f);
                *(float2*)(Mx + (size_t)(r + 8) * Mm + c) =
                    make_float2(m10 ? 1.f : 0.f, m11 ? 1.f : 0.f);
            }
        }
    }
}

// ---------------- context GEMMs: ctx = P @ V (NN, 1-pass tf32), one launch -------
__global__ __launch_bounds__(256, 3) void ctx_all(float* __restrict__ out_x,
                                                  float* __restrict__ out_y)
{
    extern __shared__ char smemc[];
    float* As = (float*)smemc;
    float* Bs = As + DEPTH_NN * ASTG32;
    int z = blockIdx.z;
    int which = (z >= 64) ? 1 : 0;
    int b = which ? (z - 64) : z;
    const float* P = (which ? g_Py : g_Px) + (size_t)b * Mm * Mm;
    const float* V = (which ? g_Vy : g_Vx) + (size_t)b * Mm * Dd;
    float* out = which ? out_y : out_x;
    int row0 = blockIdx.y * 128, col0 = blockIdx.x * 128;

    int wid = threadIdx.x >> 5, lane = threadIdx.x & 31;
    int wm = wid >> 2, wn = wid & 3;
    int gr = lane >> 2, kc = lane & 3;
    float acc[4][4][4];
#pragma unroll
    for (int i = 0; i < 4; i++)
#pragma unroll
        for (int j = 0; j < 4; j++)
#pragma unroll
            for (int q = 0; q < 4; q++) acc[i][j][q] = 0.f;

    const float* Ap = P + (size_t)row0 * Mm;
    const float* Bp = V + col0;
    uint32_t asb = smem_u32(As), bsb = smem_u32(Bs);
    constexpr int nch = Mm / BK32;   // 32
#pragma unroll
    for (int s = 0; s < DEPTH_NN - 1; s++)
        issue_stage_nn(Ap, Mm, Bp, Dd, s, nch, asb, bsb);
    for (int c = 0; c < nch; c++) {
        asm volatile("cp.async.wait_group 1;" ::: "memory");
        __syncthreads();
        issue_stage_nn(Ap, Mm, Bp, Dd, c + DEPTH_NN - 1, nch, asb, bsb);
        int buf = c % DEPTH_NN;
        compute_chunk_nn(As + buf * ASTG32, Bs + buf * BSTG_NN, acc, wm, wn, gr, kc);
    }

    float* O = out + (size_t)b * Mm * Dd;
#pragma unroll
    for (int mt = 0; mt < 4; mt++) {
        int r = row0 + wm * 64 + mt * 16 + gr;
#pragma unroll
        for (int nt = 0; nt < 4; nt++) {
            int c = col0 + wn * 32 + nt * 8 + kc * 2;
            *(float2*)(O + (size_t)r * Dd + c) =
                make_float2(acc[mt][nt][0], acc[mt][nt][1]);
            *(float2*)(O + (size_t)(r + 8) * Dd + c) =
                make_float2(acc[mt][nt][2], acc[mt][nt][3]);
        }
    }
}

// ---------------- mask normalization (dtype-agnostic) ----------------------------
__global__ void norm_masks_kernel(const unsigned int* __restrict__ mx_in,
                                  const unsigned int* __restrict__ my_in)
{
    const unsigned int* in = (blockIdx.x == 0) ? mx_in : my_in;
    unsigned char* out = (blockIdx.x == 0) ? g_mx : g_my;
    int n = (blockIdx.x == 0) ? Bb * Mm : BSs * Mm;

    __shared__ int s_flag;
    if (threadIdx.x == 0) s_flag = 0;
    __syncthreads();
    int local = 0;
    for (int i = threadIdx.x; i < n / 4; i += blockDim.x)
        if (in[i] > 1u) local = 1;
    if (local) atomicOr(&s_flag, 1);
    __syncthreads();
    bool byte_packed = (s_flag != 0);

    const unsigned char* inb = (const unsigned char*)in;
    for (int i = threadIdx.x; i < n; i += blockDim.x)
        out[i] = byte_packed ? (inb[i] != 0 ? 1 : 0) : (in[i] != 0u ? 1 : 0);
}

// ---------------- all softmaxes in one launch --------------------------------------
// blocks [0,32768): sx -> g_Px (perm, tf32); [32768,36864): sy -> g_Py (perm, tf32);
// [36864,69632): pxy in place (raw fp32).
__global__ __launch_bounds__(256) void softmax_all(
    float* __restrict__ sx, float* __restrict__ sy, float* __restrict__ pxy)
{
    int bid = blockIdx.x;
    const float* p;
    float* o;
    bool perm;
    if (bid < 32768) {
        p = sx + (size_t)bid * Mm; o = g_Px + (size_t)bid * Mm; perm = true;
    } else if (bid < 36864) {
        int r = bid - 32768;
        p = sy + (size_t)r * Mm; o = g_Py + (size_t)r * Mm; perm = true;
    } else {
        int r = bid - 36864;
        p = pxy + (size_t)r * Mm; o = pxy + (size_t)r * Mm; perm = false;
    }
    int t = threadIdx.x;

    float v0 = p[t];
    float v1 = p[t + 256];
    float m = fmaxf(v0, v1);
#pragma unroll
    for (int off = 16; off; off >>= 1)
        m = fmaxf(m, __shfl_xor_sync(0xffffffffu, m, off));
    __shared__ float smax[8], ssum[8];
    if ((t & 31) == 0) smax[t >> 5] = m;
    __syncthreads();
    float bm = smax[0];
#pragma unroll
    for (int i = 1; i < 8; i++) bm = fmaxf(bm, smax[i]);

    float e0 = __expf(v0 - bm);
    float e1 = __expf(v1 - bm);
    float s = e0 + e1;
#pragma unroll
    for (int off = 16; off; off >>= 1)
        s += __shfl_xor_sync(0xffffffffu, s, off);
    if ((t & 31) == 0) ssum[t >> 5] = s;
    __syncthreads();
    float tot = 0.f;
#pragma unroll
    for (int i = 0; i < 8; i++) tot += ssum[i];
    float inv = 1.0f / tot;
    if (perm) {
        o[sp(t)] = tf32_rna(e0 * inv);
        o[sp(t + 256)] = tf32_rna(e1 * inv);
    } else {
        o[t] = e0 * inv;
        o[t + 256] = e1 * inv;
    }
}

// ---------------- y_len -------------------------------------------------------------
__global__ void ylen_kernel(float* __restrict__ out)
{
    int t = threadIdx.x;
    if (t >= 64) return;
    int s = t & 7;
    int sum = 0;
    for (int j = 0; j < Mm; j++) sum += g_my[s * Mm + j] ? 1 : 0;
    out[t] = (float)sum;
}

// ---------------- launch --------------------------------------------------------------
extern "C" void kernel_launch(void* const* d_in, const int* in_sizes, int n_in,
                              void* d_out, int out_size)
{
    const float* x  = (const float*)d_in[0];
    const float* y  = (const float*)d_in[1];
    const unsigned int* mask_x = (const unsigned int*)d_in[2];
    const unsigned int* mask_y = (const unsigned int*)d_in[3];
    const float* Wq = (const float*)d_in[4];
    const float* Wk = (const float*)d_in[5];
    const float* Wv = (const float*)d_in[6];

    float* out = (float*)d_out;
    float* out_ctx_x = out;                    // 64*512*256
    float* out_ctx_y = out + 8388608;          // 8*512*256
    float* out_sx    = out + 9437184;          // 64*512*512
    float* out_sy    = out + 26214400;         // 8*512*512
    float* out_pxy   = out + 28311552;         // 64*512*512
    float* out_mxy   = out + 45088768;         // 64*512*512
    float* out_ylen  = out + 61865984;         // 64

    cudaFuncSetAttribute(proj_kernel, cudaFuncAttributeMaxDynamicSharedMemorySize, DSMEM_BF);
    cudaFuncSetAttribute(scores_all, cudaFuncAttributeMaxDynamicSharedMemorySize, DSMEM_BF);
    cudaFuncSetAttribute(ctx_all, cudaFuncAttributeMaxDynamicSharedMemorySize, DSMEM_NN);

    dim3 blk(256);

    norm_masks_kernel<<<2, 1024>>>(mask_x, mask_y);                          // 1
    {
        constexpr size_t TOT = (size_t)Bb * Mm * Dd + (size_t)BSs * Mm * Dd
                             + 3 * (size_t)Dd * Dd;
        split_all<<<(unsigned)((TOT + 255) / 256), 256>>>(x, y, Wq, Wk, Wv);  // 2
    }
    proj_kernel<<<dim3(2, 256, 6), blk, DSMEM_BF>>>();                       // 3
    scores_all<<<dim3(4, 4, 136), blk, DSMEM_BF>>>(out_sx, out_sy,
                                                   out_pxy, out_mxy);        // 4
    softmax_all<<<69632, 256>>>(out_sx, out_sy, out_pxy);                    // 5
    ctx_all<<<dim3(2, 4, 72), blk, DSMEM_NN>>>(out_ctx_x, out_ctx_y);        // 6
    ylen_kernel<<<1, 64>>>(out_ylen);                                        // 7
}

// round 12
// speedup vs baseline: 1.9282x; 1.9282x over previous
#include <cuda_runtime.h>
#include <cuda_bf16.h>
#include <cstdint>

constexpr int Bb  = 64;
constexpr int BSs = 8;
constexpr int Mm  = 512;
constexpr int Dd  = 256;
constexpr float NEG_FILL_F = -10000000000.0f;

// bf16 fused path: chunk = 32 bf16 k; stage = 4 tiles (Ahi,Alo,Bhi,Blo) x 8KB
constexpr int DEPTH_BF = 3;
constexpr int TSZ     = 8192;                          // bytes per tile
constexpr int BSTAGE  = 4 * TSZ;                       // 32KB per stage
constexpr int DSMEM_BF = DEPTH_BF * BSTAGE;            // 98304 B (96KB), 2 CTAs/SM
// fp32 NN path (ctx): BK=16 fp32
constexpr int DEPTH_NN = 4;
constexpr int BK32   = 16;
constexpr int BNNP   = 136;
constexpr int ASTG32   = 128 * BK32;                   // floats
constexpr int BSTG_NN  = BK32 * BNNP;                  // floats
constexpr int DSMEM_NN = DEPTH_NN * (ASTG32 + BSTG_NN) * 4;  // 67584 B

// ---------------- scratch ------------------------------------------------------
__device__ __nv_bfloat16 g_x2[(size_t)Bb * Mm * 2 * Dd];   // [hi|lo] width 512
__device__ __nv_bfloat16 g_y2[(size_t)BSs * Mm * 2 * Dd];
__device__ __nv_bfloat16 g_W2[3][(size_t)Dd * 2 * Dd];
__device__ __nv_bfloat16 g_Qx2[(size_t)Bb * Mm * 2 * Dd];
__device__ __nv_bfloat16 g_Kx2[(size_t)Bb * Mm * 2 * Dd];
__device__ __nv_bfloat16 g_Qy2[(size_t)BSs * Mm * 2 * Dd];
__device__ __nv_bfloat16 g_Ky2[(size_t)BSs * Mm * 2 * Dd];
__device__ float g_Vx[(size_t)Bb * Mm * Dd];        // V fp32 tf32-rna
__device__ float g_Vy[(size_t)BSs * Mm * Dd];
__device__ float g_Px[(size_t)Bb * Mm * Mm];        // probs tf32-rna, sp-permuted
__device__ float g_Py[(size_t)BSs * Mm * Mm];
__device__ unsigned char g_mx[Bb * Mm];
__device__ unsigned char g_my[BSs * Mm];

// ---------------- helpers ------------------------------------------------------
__device__ __forceinline__ int sp(int k) {          // involution, used for P only
    return (k & ~15) | ((k & 3) << 2) | ((k >> 2) & 3);
}
__device__ __forceinline__ float tf32_rna(float a) {
    uint32_t o;
    asm("cvt.rna.tf32.f32 %0, %1;" : "=r"(o) : "f"(a));
    return __uint_as_float(o);
}
__device__ __forceinline__ uint32_t smem_u32(const void* p) {
    uint32_t a;
    asm("{ .reg .u64 t; cvta.to.shared.u64 t, %1; cvt.u32.u64 %0, t; }"
        : "=r"(a) : "l"(p));
    return a;
}
__device__ __forceinline__ void cpa16(uint32_t dst, const void* src) {
    asm volatile("cp.async.cg.shared.global [%0], [%1], 16;"
                 :: "r"(dst), "l"(src) : "memory");
}
__device__ __forceinline__ void ldm_x4(uint32_t* r, uint32_t addr) {
    asm volatile("ldmatrix.sync.aligned.m8n8.x4.shared.b16 {%0,%1,%2,%3}, [%4];"
        : "=r"(r[0]), "=r"(r[1]), "=r"(r[2]), "=r"(r[3]) : "r"(addr));
}
__device__ __forceinline__ void mma_bf16(float* c, const uint32_t* a,
                                         uint32_t b0, uint32_t b1) {
    asm volatile(
        "mma.sync.aligned.m16n8k16.row.col.f32.bf16.bf16.f32 "
        "{%0,%1,%2,%3}, {%4,%5,%6,%7}, {%8,%9}, {%0,%1,%2,%3};"
        : "+f"(c[0]), "+f"(c[1]), "+f"(c[2]), "+f"(c[3])
        : "r"(a[0]), "r"(a[1]), "r"(a[2]), "r"(a[3]), "r"(b0), "r"(b1));
}
__device__ __forceinline__ void mma_tf32(float* c, const uint32_t* a, const uint32_t* b) {
    asm volatile(
        "mma.sync.aligned.m16n8k8.row.col.f32.tf32.tf32.f32 "
        "{%0,%1,%2,%3}, {%4,%5,%6,%7}, {%8,%9}, {%0,%1,%2,%3};"
        : "+f"(c[0]), "+f"(c[1]), "+f"(c[2]), "+f"(c[3])
        : "r"(a[0]), "r"(a[1]), "r"(a[2]), "r"(a[3]), "r"(b[0]), "r"(b[1]));
}

// ============================ fused bf16 NT GEMM path ==========================
// Per 32-k chunk, stage 4 tiles (Ahi,Alo,Bhi,Blo), each 128 rows x 64B.
// Slot swizzle (4 slots of 16B / row): phys_slot = g ^ ((row>>1)&3).
// One chunk issues all three product terms hi*hi + lo*hi + hi*lo.
__device__ __forceinline__ void issue_stage_f(
    const __nv_bfloat16* __restrict__ A, const __nv_bfloat16* __restrict__ B,
    int c, int nch, uint32_t sb)
{
    if (c < nch) {
        uint32_t sd = sb + (c % DEPTH_BF) * BSTAGE;
        int acol = c * 32;
#pragma unroll
        for (int j = 0; j < 2; j++) {
            int idx = threadIdx.x + 256 * j;
            int row = idx >> 2, slot = idx & 3;
            int g = slot ^ ((row >> 1) & 3);
            uint32_t so = row * 64 + slot * 16;
            const __nv_bfloat16* ap = A + (size_t)row * 512 + acol + g * 8;
            const __nv_bfloat16* bp = B + (size_t)row * 512 + acol + g * 8;
            cpa16(sd + so, ap);                       // A hi
            cpa16(sd + TSZ + so, ap + 256);           // A lo
            cpa16(sd + 2 * TSZ + so, bp);             // B hi
            cpa16(sd + 3 * TSZ + so, bp + 256);       // B lo
        }
    }
    asm volatile("cp.async.commit_group;" ::: "memory");
}

// warp tile 64(m) x 32(n); 8 warps 2x4 over 128x128 CTA tile; 32 k per chunk.
__device__ __forceinline__ void compute_chunk_f(
    uint32_t sd, float (&acc)[4][4][4], int wm, int wn, int lane)
{
    int j = lane >> 3, rin = lane & 7;
    int jk = j >> 1, jo = (j & 1) * 8;
    int rowA = wm * 64 + jo + rin;
    int rowB = wn * 32 + jo + rin;
    int swA = (rowA >> 1) & 3, swB = (rowB >> 1) & 3;
#pragma unroll
    for (int ks = 0; ks < 2; ks++) {
        uint32_t slA = (uint32_t)(((ks * 2 + jk) ^ swA) * 16);
        uint32_t slB = (uint32_t)(((ks * 2 + jk) ^ swB) * 16);
        uint32_t bhi[2][4], blo[2][4];
#pragma unroll
        for (int np = 0; np < 2; np++) {
            ldm_x4(bhi[np], sd + 2 * TSZ + (rowB + np * 16) * 64 + slB);
            ldm_x4(blo[np], sd + 3 * TSZ + (rowB + np * 16) * 64 + slB);
        }
#pragma unroll
        for (int mt = 0; mt < 4; mt++) {
            uint32_t ahi[4], alo[4];
            ldm_x4(ahi, sd + (rowA + mt * 16) * 64 + slA);
            ldm_x4(alo, sd + TSZ + (rowA + mt * 16) * 64 + slA);
#pragma unroll
            for (int nt = 0; nt < 4; nt++) {
                uint32_t b0 = bhi[nt >> 1][nt & 1], b1 = bhi[nt >> 1][(nt & 1) + 2];
                mma_bf16(acc[mt][nt], ahi, b0, b1);
                mma_bf16(acc[mt][nt], alo, b0, b1);
                mma_bf16(acc[mt][nt], ahi,
                         blo[nt >> 1][nt & 1], blo[nt >> 1][(nt & 1) + 2]);
            }
        }
    }
}

__device__ __forceinline__ void gemm_bf16(
    const __nv_bfloat16* __restrict__ A, const __nv_bfloat16* __restrict__ B,
    float (&acc)[4][4][4], uint32_t sb, int wm, int wn, int lane)
{
    constexpr int nch = 8;   // 8 chunks of 32 k over K=256, fused 3 terms
#pragma unroll
    for (int s = 0; s < DEPTH_BF - 1; s++)
        issue_stage_f(A, B, s, nch, sb);
    for (int c = 0; c < nch; c++) {
        asm volatile("cp.async.wait_group 1;" ::: "memory");
        __syncthreads();
        issue_stage_f(A, B, c + DEPTH_BF - 1, nch, sb);
        compute_chunk_f(sb + (c % DEPTH_BF) * BSTAGE, acc, wm, wn, lane);
    }
}

#define BF16_SETUP()                                        \
    extern __shared__ char smem[];                          \
    uint32_t sb = smem_u32(smem);                           \
    int wid = threadIdx.x >> 5, lane = threadIdx.x & 31;    \
    int wm = wid >> 2, wn = wid & 3;                        \
    int gr = lane >> 2, kc = lane & 3;                      \
    float acc[4][4][4];                                     \
    _Pragma("unroll") for (int i = 0; i < 4; i++)           \
    _Pragma("unroll") for (int jj = 0; jj < 4; jj++)        \
    _Pragma("unroll") for (int q = 0; q < 4; q++) acc[i][jj][q] = 0.f;

// ============================ fp32 NN path (ctx only) ==========================
__device__ __forceinline__ void issue_stage_nn(
    const float* __restrict__ A, int lda, const float* __restrict__ B, int ldb,
    int c, int nch, uint32_t asb, uint32_t bsb)
{
    if (c < nch) {
        int kc = c;
        int buf = c & (DEPTH_NN - 1);
        uint32_t ad = asb + buf * (ASTG32 * 4);
        uint32_t bd = bsb + buf * (BSTG_NN * 4);
#pragma unroll
        for (int j = 0; j < 2; j++) {             // A: 128 rows x 4 slots
            int idx = threadIdx.x + 256 * j;
            int row = idx >> 2, slot = idx & 3;
            int g = slot ^ (row & 3);
            cpa16(ad + row * 64 + slot * 16, A + (size_t)row * lda + kc * BK32 + g * 4);
        }
#pragma unroll
        for (int j = 0; j < 2; j++) {             // B: 16 k-rows x 32 segs
            int idx = threadIdx.x + 256 * j;
            int row = idx >> 5, seg = idx & 31;
            cpa16(bd + (row * BNNP + seg * 4) * 4,
                  B + (size_t)(kc * BK32 + row) * ldb + seg * 4);
        }
    }
    asm volatile("cp.async.commit_group;" ::: "memory");
}

__device__ __forceinline__ void compute_chunk_nn(
    const float* __restrict__ As, const float* __restrict__ Bs,
    float (&acc)[4][4][4], int wm, int wn, int gr, int kc)
{
    const int slot4 = (kc ^ (gr & 3)) * 4;
    uint32_t a[2][4][4], b[2][4][2];
#pragma unroll
    for (int mt = 0; mt < 4; mt++) {
        int r0 = wm * 64 + mt * 16 + gr;
        float4 u = *(const float4*)(As + r0 * BK32 + slot4);
        float4 w = *(const float4*)(As + (r0 + 8) * BK32 + slot4);
        a[0][mt][0] = __float_as_uint(u.x); a[0][mt][1] = __float_as_uint(w.x);
        a[0][mt][2] = __float_as_uint(u.y); a[0][mt][3] = __float_as_uint(w.y);
        a[1][mt][0] = __float_as_uint(u.z); a[1][mt][1] = __float_as_uint(w.z);
        a[1][mt][2] = __float_as_uint(u.w); a[1][mt][3] = __float_as_uint(w.w);
    }
#pragma unroll
    for (int k8 = 0; k8 < 2; k8++)
#pragma unroll
        for (int nt = 0; nt < 4; nt++) {
            const float* p = Bs + (k8 * 8 + kc) * BNNP + wn * 32 + nt * 8 + gr;
            b[k8][nt][0] = __float_as_uint(p[0]);
            b[k8][nt][1] = __float_as_uint(p[4 * BNNP]);
        }
#pragma unroll
    for (int k8 = 0; k8 < 2; k8++)
#pragma unroll
        for (int mt = 0; mt < 4; mt++)
#pragma unroll
            for (int nt = 0; nt < 4; nt++)
                mma_tf32(acc[mt][nt], a[k8][mt], b[k8][nt]);
}

// ---------------- fused split: x/y/W -> bf16 [hi | lo] --------------------------
__global__ void split_all(const float* __restrict__ x, const float* __restrict__ y,
                          const float* __restrict__ Wq, const float* __restrict__ Wk,
                          const float* __restrict__ Wv)
{
    constexpr size_t NX = (size_t)Bb * Mm * Dd;
    constexpr size_t NY = (size_t)BSs * Mm * Dd;
    constexpr size_t NW = (size_t)Dd * Dd;
    size_t i = (size_t)blockIdx.x * blockDim.x + threadIdx.x;
    if (i < NX) {
        int r = (int)(i / Dd), c = (int)(i % Dd);
        float v = x[i];
        __nv_bfloat16 h = __float2bfloat16(v);
        g_x2[(size_t)r * 512 + c] = h;
        g_x2[(size_t)r * 512 + 256 + c] = __float2bfloat16(v - __bfloat162float(h));
    } else if (i < NX + NY) {
        size_t e = i - NX;
        int r = (int)(e / Dd), c = (int)(e % Dd);
        float v = y[e];
        __nv_bfloat16 h = __float2bfloat16(v);
        g_y2[(size_t)r * 512 + c] = h;
        g_y2[(size_t)r * 512 + 256 + c] = __float2bfloat16(v - __bfloat162float(h));
    } else if (i < NX + NY + 3 * NW) {
        size_t j = i - NX - NY;
        int w = (int)(j / NW);
        size_t e = j % NW;
        int r = (int)(e / Dd), c = (int)(e % Dd);
        const float* W = (w == 0) ? Wq : (w == 1) ? Wk : Wv;
        float v = W[e];
        __nv_bfloat16 h = __float2bfloat16(v);
        g_W2[w][(size_t)r * 512 + c] = h;
        g_W2[w][(size_t)r * 512 + 256 + c] = __float2bfloat16(v - __bfloat162float(h));
    }
}

// ---------------- projections (fused 3-term bf16) -------------------------------
__global__ __launch_bounds__(256, 2) void proj_kernel()
{
    int z = blockIdx.z;
    bool isY = z >= 3;
    if (isY && blockIdx.y >= 32) return;
    int mat = z % 3;
    const __nv_bfloat16* A2 = isY ? g_y2 : g_x2;
    const __nv_bfloat16* B2 = g_W2[mat];
    int row0 = blockIdx.y * 128, col0 = blockIdx.x * 128;

    BF16_SETUP();
    gemm_bf16(A2 + (size_t)row0 * 512, B2 + (size_t)col0 * 512,
              acc, sb, wm, wn, lane);

    if (mat < 2) {
        __nv_bfloat16* Q2 = (mat == 0) ? (isY ? g_Qy2 : g_Qx2) : (isY ? g_Ky2 : g_Kx2);
#pragma unroll
        for (int mt = 0; mt < 4; mt++) {
            int r = row0 + wm * 64 + mt * 16 + gr;
#pragma unroll
            for (int nt = 0; nt < 4; nt++) {
                int c = col0 + wn * 32 + nt * 8 + kc * 2;
#pragma unroll
                for (int h2 = 0; h2 < 2; h2++) {
                    int rr = r + h2 * 8;
                    float v0 = acc[mt][nt][h2 * 2], v1 = acc[mt][nt][h2 * 2 + 1];
                    __nv_bfloat16 h0 = __float2bfloat16(v0);
                    __nv_bfloat16 h1 = __float2bfloat16(v1);
                    __nv_bfloat162 hi; hi.x = h0; hi.y = h1;
                    __nv_bfloat162 lo;
                    lo.x = __float2bfloat16(v0 - __bfloat162float(h0));
                    lo.y = __float2bfloat16(v1 - __bfloat162float(h1));
                    *(__nv_bfloat162*)(Q2 + (size_t)rr * 512 + c) = hi;
                    *(__nv_bfloat162*)(Q2 + (size_t)rr * 512 + 256 + c) = lo;
                }
            }
        }
    } else {
        float* V = isY ? g_Vy : g_Vx;
#pragma unroll
        for (int mt = 0; mt < 4; mt++) {
            int r = row0 + wm * 64 + mt * 16 + gr;
#pragma unroll
            for (int nt = 0; nt < 4; nt++) {
                int c = col0 + wn * 32 + nt * 8 + kc * 2;
#pragma unroll
                for (int h2 = 0; h2 < 2; h2++) {
                    int rr = r + h2 * 8;
                    *(float2*)(V + (size_t)rr * Dd + c) =
                        make_float2(tf32_rna(acc[mt][nt][h2 * 2]),
                                    tf32_rna(acc[mt][nt][h2 * 2 + 1]));
                }
            }
        }
    }
}

// ---------------- ALL masked score GEMMs in one launch ----------------------------
// z in [0,64): scores_x batch z; [64,128): scores_xy zb=z-64 (+ mask_xy);
// [128,136): scores_y zb=z-128.
__global__ __launch_bounds__(256, 2) void scores_all(
    float* __restrict__ sx, float* __restrict__ sy,
    float* __restrict__ pxy, float* __restrict__ mxy)
{
    int z = blockIdx.z;
    const __nv_bfloat16 *A, *Bp;
    const unsigned char *mr, *mc;
    float* C;
    float* Mx = nullptr;
    if (z < 64) {
        A = g_Qx2 + (size_t)z * Mm * 512; Bp = g_Kx2 + (size_t)z * Mm * 512;
        mr = g_mx + z * Mm; mc = mr;
        C = sx + (size_t)z * Mm * Mm;
    } else if (z < 128) {
        int zb = z - 64;
        int n = zb >> 3, s = zb & 7, b = s * 8 + n;
        A = g_Qx2 + (size_t)b * Mm * 512; Bp = g_Ky2 + (size_t)s * Mm * 512;
        mr = g_mx + b * Mm; mc = g_my + s * Mm;
        C = pxy + (size_t)zb * Mm * Mm;
        Mx = mxy + (size_t)zb * Mm * Mm;
    } else {
        int zb = z - 128;
        A = g_Qy2 + (size_t)zb * Mm * 512; Bp = g_Ky2 + (size_t)zb * Mm * 512;
        mr = g_my + zb * Mm; mc = mr;
        C = sy + (size_t)zb * Mm * Mm;
    }
    int row0 = blockIdx.y * 128, col0 = blockIdx.x * 128;

    BF16_SETUP();
    gemm_bf16(A + (size_t)row0 * 512, Bp + (size_t)col0 * 512,
              acc, sb, wm, wn, lane);

#pragma unroll
    for (int mt = 0; mt < 4; mt++) {
        int r = row0 + wm * 64 + mt * 16 + gr;
        bool rm0 = mr[r] != 0, rm1 = mr[r + 8] != 0;
#pragma unroll
        for (int nt = 0; nt < 4; nt++) {
            int c = col0 + wn * 32 + nt * 8 + kc * 2;
            bool c0 = mc[c] != 0, c1 = mc[c + 1] != 0;
            bool m00 = rm0 && c0, m01 = rm0 && c1;
            bool m10 = rm1 && c0, m11 = rm1 && c1;
            float2 v0, v1;
            v0.x = m00 ? acc[mt][nt][0] : NEG_FILL_F;
            v0.y = m01 ? acc[mt][nt][1] : NEG_FILL_F;
            v1.x = m10 ? acc[mt][nt][2] : NEG_FILL_F;
            v1.y = m11 ? acc[mt][nt][3] : NEG_FILL_F;
            *(float2*)(C + (size_t)r * Mm + c) = v0;
            *(float2*)(C + (size_t)(r + 8) * Mm + c) = v1;
            if (Mx) {
                *(float2*)(Mx + (size_t)r * Mm + c) =
                    make_float2(m00 ? 1.f : 0.f, m01 ? 1.f : 0.f);
                *(float2*)(Mx + (size_t)(r + 8) * Mm + c) =
                    make_float2(m10 ? 1.f : 0.f, m11 ? 1.f : 0.f);
            }
        }
    }
}

// ---------------- context GEMMs: ctx = P @ V (NN, 1-pass tf32), one launch -------
__global__ __launch_bounds__(256, 2) void ctx_all(float* __restrict__ out_x,
                                                  float* __restrict__ out_y)
{
    extern __shared__ char smemc[];
    float* As = (float*)smemc;
    float* Bs = As + DEPTH_NN * ASTG32;
    int z = blockIdx.z;
    int which = (z >= 64) ? 1 : 0;
    int b = which ? (z - 64) : z;
    const float* P = (which ? g_Py : g_Px) + (size_t)b * Mm * Mm;
    const float* V = (which ? g_Vy : g_Vx) + (size_t)b * Mm * Dd;
    float* out = which ? out_y : out_x;
    int row0 = blockIdx.y * 128, col0 = blockIdx.x * 128;

    int wid = threadIdx.x >> 5, lane = threadIdx.x & 31;
    int wm = wid >> 2, wn = wid & 3;
    int gr = lane >> 2, kc = lane & 3;
    float acc[4][4][4];
#pragma unroll
    for (int i = 0; i < 4; i++)
#pragma unroll
        for (int j = 0; j < 4; j++)
#pragma unroll
            for (int q = 0; q < 4; q++) acc[i][j][q] = 0.f;

    const float* Ap = P + (size_t)row0 * Mm;
    const float* Bp = V + col0;
    uint32_t asb = smem_u32(As), bsb = smem_u32(Bs);
    constexpr int nch = Mm / BK32;   // 32
#pragma unroll
    for (int s = 0; s < DEPTH_NN - 1; s++)
        issue_stage_nn(Ap, Mm, Bp, Dd, s, nch, asb, bsb);
    for (int c = 0; c < nch; c++) {
        asm volatile("cp.async.wait_group 2;" ::: "memory");
        __syncthreads();
        issue_stage_nn(Ap, Mm, Bp, Dd, c + DEPTH_NN - 1, nch, asb, bsb);
        int buf = c & (DEPTH_NN - 1);
        compute_chunk_nn(As + buf * ASTG32, Bs + buf * BSTG_NN, acc, wm, wn, gr, kc);
    }

    float* O = out + (size_t)b * Mm * Dd;
#pragma unroll
    for (int mt = 0; mt < 4; mt++) {
        int r = row0 + wm * 64 + mt * 16 + gr;
#pragma unroll
        for (int nt = 0; nt < 4; nt++) {
            int c = col0 + wn * 32 + nt * 8 + kc * 2;
            *(float2*)(O + (size_t)r * Dd + c) =
                make_float2(acc[mt][nt][0], acc[mt][nt][1]);
            *(float2*)(O + (size_t)(r + 8) * Dd + c) =
                make_float2(acc[mt][nt][2], acc[mt][nt][3]);
        }
    }
}

// ---------------- mask normalization (dtype-agnostic) ----------------------------
__global__ void norm_masks_kernel(const unsigned int* __restrict__ mx_in,
                                  const unsigned int* __restrict__ my_in)
{
    const unsigned int* in = (blockIdx.x == 0) ? mx_in : my_in;
    unsigned char* out = (blockIdx.x == 0) ? g_mx : g_my;
    int n = (blockIdx.x == 0) ? Bb * Mm : BSs * Mm;

    __shared__ int s_flag;
    if (threadIdx.x == 0) s_flag = 0;
    __syncthreads();
    int local = 0;
    for (int i = threadIdx.x; i < n / 4; i += blockDim.x)
        if (in[i] > 1u) local = 1;
    if (local) atomicOr(&s_flag, 1);
    __syncthreads();
    bool byte_packed = (s_flag != 0);

    const unsigned char* inb = (const unsigned char*)in;
    for (int i = threadIdx.x; i < n; i += blockDim.x)
        out[i] = byte_packed ? (inb[i] != 0 ? 1 : 0) : (in[i] != 0u ? 1 : 0);
}

// ---------------- all softmaxes in one launch --------------------------------------
// blocks [0,32768): sx -> g_Px (perm, tf32); [32768,36864): sy -> g_Py (perm, tf32);
// [36864,69632): pxy in place (raw fp32).
__global__ __launch_bounds__(256) void softmax_all(
    float* __restrict__ sx, float* __restrict__ sy, float* __restrict__ pxy)
{
    int bid = blockIdx.x;
    const float* p;
    float* o;
    bool perm;
    if (bid < 32768) {
        p = sx + (size_t)bid * Mm; o = g_Px + (size_t)bid * Mm; perm = true;
    } else if (bid < 36864) {
        int r = bid - 32768;
        p = sy + (size_t)r * Mm; o = g_Py + (size_t)r * Mm; perm = true;
    } else {
        int r = bid - 36864;
        p = pxy + (size_t)r * Mm; o = pxy + (size_t)r * Mm; perm = false;
    }
    int t = threadIdx.x;

    float v0 = p[t];
    float v1 = p[t + 256];
    float m = fmaxf(v0, v1);
#pragma unroll
    for (int off = 16; off; off >>= 1)
        m = fmaxf(m, __shfl_xor_sync(0xffffffffu, m, off));
    __shared__ float smax[8], ssum[8];
    if ((t & 31) == 0) smax[t >> 5] = m;
    __syncthreads();
    float bm = smax[0];
#pragma unroll
    for (int i = 1; i < 8; i++) bm = fmaxf(bm, smax[i]);

    float e0 = __expf(v0 - bm);
    float e1 = __expf(v1 - bm);
    float s = e0 + e1;
#pragma unroll
    for (int off = 16; off; off >>= 1)
        s += __shfl_xor_sync(0xffffffffu, s, off);
    if ((t & 31) == 0) ssum[t >> 5] = s;
    __syncthreads();
    float tot = 0.f;
#pragma unroll
    for (int i = 0; i < 8; i++) tot += ssum[i];
    float inv = 1.0f / tot;
    if (perm) {
        o[sp(t)] = tf32_rna(e0 * inv);
        o[sp(t + 256)] = tf32_rna(e1 * inv);
    } else {
        o[t] = e0 * inv;
        o[t + 256] = e1 * inv;
    }
}

// ---------------- y_len -------------------------------------------------------------
__global__ void ylen_kernel(float* __restrict__ out)
{
    int t = threadIdx.x;
    if (t >= 64) return;
    int s = t & 7;
    int sum = 0;
    for (int j = 0; j < Mm; j++) sum += g_my[s * Mm + j] ? 1 : 0;
    out[t] = (float)sum;
}

// ---------------- launch --------------------------------------------------------------
extern "C" void kernel_launch(void* const* d_in, const int* in_sizes, int n_in,
                              void* d_out, int out_size)
{
    const float* x  = (const float*)d_in[0];
    const float* y  = (const float*)d_in[1];
    const unsigned int* mask_x = (const unsigned int*)d_in[2];
    const unsigned int* mask_y = (const unsigned int*)d_in[3];
    const float* Wq = (const float*)d_in[4];
    const float* Wk = (const float*)d_in[5];
    const float* Wv = (const float*)d_in[6];

    float* out = (float*)d_out;
    float* out_ctx_x = out;                    // 64*512*256
    float* out_ctx_y = out + 8388608;          // 8*512*256
    float* out_sx    = out + 9437184;          // 64*512*512
    float* out_sy    = out + 26214400;         // 8*512*512
    float* out_pxy   = out + 28311552;         // 64*512*512
    float* out_mxy   = out + 45088768;         // 64*512*512
    float* out_ylen  = out + 61865984;         // 64

    cudaFuncSetAttribute(proj_kernel, cudaFuncAttributeMaxDynamicSharedMemorySize, DSMEM_BF);
    cudaFuncSetAttribute(scores_all, cudaFuncAttributeMaxDynamicSharedMemorySize, DSMEM_BF);
    cudaFuncSetAttribute(ctx_all, cudaFuncAttributeMaxDynamicSharedMemorySize, DSMEM_NN);

    dim3 blk(256);

    norm_masks_kernel<<<2, 1024>>>(mask_x, mask_y);                          // 1
    {
        constexpr size_t TOT = (size_t)Bb * Mm * Dd + (size_t)BSs * Mm * Dd
                             + 3 * (size_t)Dd * Dd;
        split_all<<<(unsigned)((TOT + 255) / 256), 256>>>(x, y, Wq, Wk, Wv);  // 2
    }
    proj_kernel<<<dim3(2, 256, 6), blk, DSMEM_BF>>>();                       // 3
    scores_all<<<dim3(4, 4, 136), blk, DSMEM_BF>>>(out_sx, out_sy,
                                                   out_pxy, out_mxy);        // 4
    softmax_all<<<69632, 256>>>(out_sx, out_sy, out_pxy);                    // 5
    ctx_all<<<dim3(2, 4, 72), blk, DSMEM_NN>>>(out_ctx_x, out_ctx_y);        // 6
    ylen_kernel<<<1, 64>>>(out_ylen);                                        // 7
}

// round 13
// speedup vs baseline: 2.0182x; 1.0467x over previous
#include <cuda_runtime.h>
#include <cuda_bf16.h>
#include <cstdint>

constexpr int Bb  = 64;
constexpr int BSs = 8;
constexpr int Mm  = 512;
constexpr int Dd  = 256;
constexpr float NEG_FILL_F = -10000000000.0f;

// bf16 fused path: chunk = 32 bf16 k; stage = 4 tiles (Ahi,Alo,Bhi,Blo) x 8KB
constexpr int DEPTH_BF = 3;
constexpr int TSZ     = 8192;
constexpr int BSTAGE  = 4 * TSZ;                       // 32KB per stage
constexpr int DSMEM_BF = DEPTH_BF * BSTAGE;            // 96KB, 2 CTAs/SM
// fp32 NN path (ctx): BK=16 fp32
constexpr int DEPTH_NN = 4;
constexpr int BK32   = 16;
constexpr int BNNP   = 136;
constexpr int ASTG32   = 128 * BK32;                   // floats
constexpr int BSTG_NN  = BK32 * BNNP;                  // floats
constexpr int DSMEM_NN = DEPTH_NN * (ASTG32 + BSTG_NN) * 4;  // 67584 B

// ---------------- scratch ------------------------------------------------------
__device__ __nv_bfloat16 g_x2[(size_t)Bb * Mm * 2 * Dd];   // [hi|lo] width 512
__device__ __nv_bfloat16 g_y2[(size_t)BSs * Mm * 2 * Dd];
__device__ __nv_bfloat16 g_W2[3][(size_t)Dd * 2 * Dd];
__device__ __nv_bfloat16 g_Qx2[(size_t)Bb * Mm * 2 * Dd];
__device__ __nv_bfloat16 g_Kx2[(size_t)Bb * Mm * 2 * Dd];
__device__ __nv_bfloat16 g_Qy2[(size_t)BSs * Mm * 2 * Dd];
__device__ __nv_bfloat16 g_Ky2[(size_t)BSs * Mm * 2 * Dd];
__device__ float g_Vx[(size_t)Bb * Mm * Dd];        // V fp32 tf32-rna
__device__ float g_Vy[(size_t)BSs * Mm * Dd];
// per-(batch,row,tile16) softmax partials: (max, sumexp). batches: 0..63 x, 64..71 y
__device__ float2 g_part[(size_t)(Bb + BSs) * Mm * 16];
__device__ unsigned char g_mx[Bb * Mm];
__device__ unsigned char g_my[BSs * Mm];

// ---------------- helpers ------------------------------------------------------
__device__ __forceinline__ float tf32_rna(float a) {
    uint32_t o;
    asm("cvt.rna.tf32.f32 %0, %1;" : "=r"(o) : "f"(a));
    return __uint_as_float(o);
}
__device__ __forceinline__ uint32_t smem_u32(const void* p) {
    uint32_t a;
    asm("{ .reg .u64 t; cvta.to.shared.u64 t, %1; cvt.u32.u64 %0, t; }"
        : "=r"(a) : "l"(p));
    return a;
}
__device__ __forceinline__ void cpa16(uint32_t dst, const void* src) {
    asm volatile("cp.async.cg.shared.global [%0], [%1], 16;"
                 :: "r"(dst), "l"(src) : "memory");
}
__device__ __forceinline__ void sts32(uint32_t addr, float v) {
    asm volatile("st.shared.f32 [%0], %1;" :: "r"(addr), "f"(v) : "memory");
}
__device__ __forceinline__ void ldm_x4(uint32_t* r, uint32_t addr) {
    asm volatile("ldmatrix.sync.aligned.m8n8.x4.shared.b16 {%0,%1,%2,%3}, [%4];"
        : "=r"(r[0]), "=r"(r[1]), "=r"(r[2]), "=r"(r[3]) : "r"(addr));
}
__device__ __forceinline__ void mma_bf16(float* c, const uint32_t* a,
                                         uint32_t b0, uint32_t b1) {
    asm volatile(
        "mma.sync.aligned.m16n8k16.row.col.f32.bf16.bf16.f32 "
        "{%0,%1,%2,%3}, {%4,%5,%6,%7}, {%8,%9}, {%0,%1,%2,%3};"
        : "+f"(c[0]), "+f"(c[1]), "+f"(c[2]), "+f"(c[3])
        : "r"(a[0]), "r"(a[1]), "r"(a[2]), "r"(a[3]), "r"(b0), "r"(b1));
}
__device__ __forceinline__ void mma_tf32(float* c, const uint32_t* a, const uint32_t* b) {
    asm volatile(
        "mma.sync.aligned.m16n8k8.row.col.f32.tf32.tf32.f32 "
        "{%0,%1,%2,%3}, {%4,%5,%6,%7}, {%8,%9}, {%0,%1,%2,%3};"
        : "+f"(c[0]), "+f"(c[1]), "+f"(c[2]), "+f"(c[3])
        : "r"(a[0]), "r"(a[1]), "r"(a[2]), "r"(a[3]), "r"(b[0]), "r"(b[1]));
}

// ============================ fused bf16 NT GEMM path ==========================
__device__ __forceinline__ void issue_stage_f(
    const __nv_bfloat16* __restrict__ A, const __nv_bfloat16* __restrict__ B,
    int c, int nch, uint32_t sb)
{
    if (c < nch) {
        uint32_t sd = sb + (c % DEPTH_BF) * BSTAGE;
        int acol = c * 32;
#pragma unroll
        for (int j = 0; j < 2; j++) {
            int idx = threadIdx.x + 256 * j;
            int row = idx >> 2, slot = idx & 3;
            int g = slot ^ ((row >> 1) & 3);
            uint32_t so = row * 64 + slot * 16;
            const __nv_bfloat16* ap = A + (size_t)row * 512 + acol + g * 8;
            const __nv_bfloat16* bp = B + (size_t)row * 512 + acol + g * 8;
            cpa16(sd + so, ap);                       // A hi
            cpa16(sd + TSZ + so, ap + 256);           // A lo
            cpa16(sd + 2 * TSZ + so, bp);             // B hi
            cpa16(sd + 3 * TSZ + so, bp + 256);       // B lo
        }
    }
    asm volatile("cp.async.commit_group;" ::: "memory");
}

__device__ __forceinline__ void compute_chunk_f(
    uint32_t sd, float (&acc)[4][4][4], int wm, int wn, int lane)
{
    int j = lane >> 3, rin = lane & 7;
    int jk = j >> 1, jo = (j & 1) * 8;
    int rowA = wm * 64 + jo + rin;
    int rowB = wn * 32 + jo + rin;
    int swA = (rowA >> 1) & 3, swB = (rowB >> 1) & 3;
#pragma unroll
    for (int ks = 0; ks < 2; ks++) {
        uint32_t slA = (uint32_t)(((ks * 2 + jk) ^ swA) * 16);
        uint32_t slB = (uint32_t)(((ks * 2 + jk) ^ swB) * 16);
        uint32_t bhi[2][4], blo[2][4];
#pragma unroll
        for (int np = 0; np < 2; np++) {
            ldm_x4(bhi[np], sd + 2 * TSZ + (rowB + np * 16) * 64 + slB);
            ldm_x4(blo[np], sd + 3 * TSZ + (rowB + np * 16) * 64 + slB);
        }
#pragma unroll
        for (int mt = 0; mt < 4; mt++) {
            uint32_t ahi[4], alo[4];
            ldm_x4(ahi, sd + (rowA + mt * 16) * 64 + slA);
            ldm_x4(alo, sd + TSZ + (rowA + mt * 16) * 64 + slA);
#pragma unroll
            for (int nt = 0; nt < 4; nt++) {
                uint32_t b0 = bhi[nt >> 1][nt & 1], b1 = bhi[nt >> 1][(nt & 1) + 2];
                mma_bf16(acc[mt][nt], ahi, b0, b1);
                mma_bf16(acc[mt][nt], alo, b0, b1);
                mma_bf16(acc[mt][nt], ahi,
                         blo[nt >> 1][nt & 1], blo[nt >> 1][(nt & 1) + 2]);
            }
        }
    }
}

__device__ __forceinline__ void gemm_bf16(
    const __nv_bfloat16* __restrict__ A, const __nv_bfloat16* __restrict__ B,
    float (&acc)[4][4][4], uint32_t sb, int wm, int wn, int lane)
{
    constexpr int nch = 8;
#pragma unroll
    for (int s = 0; s < DEPTH_BF - 1; s++)
        issue_stage_f(A, B, s, nch, sb);
    for (int c = 0; c < nch; c++) {
        asm volatile("cp.async.wait_group 1;" ::: "memory");
        __syncthreads();
        issue_stage_f(A, B, c + DEPTH_BF - 1, nch, sb);
        compute_chunk_f(sb + (c % DEPTH_BF) * BSTAGE, acc, wm, wn, lane);
    }
}

#define BF16_SETUP()                                        \
    extern __shared__ char smem[];                          \
    uint32_t sb = smem_u32(smem);                           \
    int wid = threadIdx.x >> 5, lane = threadIdx.x & 31;    \
    int wm = wid >> 2, wn = wid & 3;                        \
    int gr = lane >> 2, kc = lane & 3;                      \
    float acc[4][4][4];                                     \
    _Pragma("unroll") for (int i = 0; i < 4; i++)           \
    _Pragma("unroll") for (int jj = 0; jj < 4; jj++)        \
    _Pragma("unroll") for (int q = 0; q < 4; q++) acc[i][jj][q] = 0.f;

// ============================ fp32 NN path (ctx only) ==========================
__device__ __forceinline__ void issue_stage_nnB(
    const float* __restrict__ B, int ldb, int c, int nch, uint32_t bsb)
{
    if (c < nch) {
        int buf = c & (DEPTH_NN - 1);
        uint32_t bd = bsb + buf * (BSTG_NN * 4);
#pragma unroll
        for (int j = 0; j < 2; j++) {             // B: 16 k-rows x 32 segs
            int idx = threadIdx.x + 256 * j;
            int row = idx >> 5, seg = idx & 31;
            cpa16(bd + (row * BNNP + seg * 4) * 4,
                  B + (size_t)(c * BK32 + row) * ldb + seg * 4);
        }
    }
    asm volatile("cp.async.commit_group;" ::: "memory");
}

__device__ __forceinline__ void compute_chunk_nn(
    const float* __restrict__ As, const float* __restrict__ Bs,
    float (&acc)[4][4][4], int wm, int wn, int gr, int kc)
{
    const int slot4 = (kc ^ (gr & 3)) * 4;
    uint32_t a[2][4][4], b[2][4][2];
#pragma unroll
    for (int mt = 0; mt < 4; mt++) {
        int r0 = wm * 64 + mt * 16 + gr;
        float4 u = *(const float4*)(As + r0 * BK32 + slot4);
        float4 w = *(const float4*)(As + (r0 + 8) * BK32 + slot4);
        a[0][mt][0] = __float_as_uint(u.x); a[0][mt][1] = __float_as_uint(w.x);
        a[0][mt][2] = __float_as_uint(u.y); a[0][mt][3] = __float_as_uint(w.y);
        a[1][mt][0] = __float_as_uint(u.z); a[1][mt][1] = __float_as_uint(w.z);
        a[1][mt][2] = __float_as_uint(u.w); a[1][mt][3] = __float_as_uint(w.w);
    }
#pragma unroll
    for (int k8 = 0; k8 < 2; k8++)
#pragma unroll
        for (int nt = 0; nt < 4; nt++) {
            const float* p = Bs + (k8 * 8 + kc) * BNNP + wn * 32 + nt * 8 + gr;
            b[k8][nt][0] = __float_as_uint(p[0]);
            b[k8][nt][1] = __float_as_uint(p[4 * BNNP]);
        }
#pragma unroll
    for (int k8 = 0; k8 < 2; k8++)
#pragma unroll
        for (int mt = 0; mt < 4; mt++)
#pragma unroll
            for (int nt = 0; nt < 4; nt++)
                mma_tf32(acc[mt][nt], a[k8][mt], b[k8][nt]);
}

// ---------------- fused split: x/y/W -> bf16 [hi | lo] --------------------------
__global__ void split_all(const float* __restrict__ x, const float* __restrict__ y,
                          const float* __restrict__ Wq, const float* __restrict__ Wk,
                          const float* __restrict__ Wv)
{
    constexpr size_t NX = (size_t)Bb * Mm * Dd;
    constexpr size_t NY = (size_t)BSs * Mm * Dd;
    constexpr size_t NW = (size_t)Dd * Dd;
    size_t i = (size_t)blockIdx.x * blockDim.x + threadIdx.x;
    if (i < NX) {
        int r = (int)(i / Dd), c = (int)(i % Dd);
        float v = x[i];
        __nv_bfloat16 h = __float2bfloat16(v);
        g_x2[(size_t)r * 512 + c] = h;
        g_x2[(size_t)r * 512 + 256 + c] = __float2bfloat16(v - __bfloat162float(h));
    } else if (i < NX + NY) {
        size_t e = i - NX;
        int r = (int)(e / Dd), c = (int)(e % Dd);
        float v = y[e];
        __nv_bfloat16 h = __float2bfloat16(v);
        g_y2[(size_t)r * 512 + c] = h;
        g_y2[(size_t)r * 512 + 256 + c] = __float2bfloat16(v - __bfloat162float(h));
    } else if (i < NX + NY + 3 * NW) {
        size_t j = i - NX - NY;
        int w = (int)(j / NW);
        size_t e = j % NW;
        int r = (int)(e / Dd), c = (int)(e % Dd);
        const float* W = (w == 0) ? Wq : (w == 1) ? Wk : Wv;
        float v = W[e];
        __nv_bfloat16 h = __float2bfloat16(v);
        g_W2[w][(size_t)r * 512 + c] = h;
        g_W2[w][(size_t)r * 512 + 256 + c] = __float2bfloat16(v - __bfloat162float(h));
    }
}

// ---------------- projections (fused 3-term bf16), exact grid -------------------
// grid (2, 288, 3): y<256 -> x rows, y>=256 -> y rows; z = mat.
__global__ __launch_bounds__(256, 2) void proj_kernel()
{
    bool isY = blockIdx.y >= 256;
    int mat = blockIdx.z;
    const __nv_bfloat16* A2 = isY ? g_y2 : g_x2;
    const __nv_bfloat16* B2 = g_W2[mat];
    int row0 = (isY ? (blockIdx.y - 256) : blockIdx.y) * 128;
    int col0 = blockIdx.x * 128;

    BF16_SETUP();
    gemm_bf16(A2 + (size_t)row0 * 512, B2 + (size_t)col0 * 512,
              acc, sb, wm, wn, lane);

    if (mat < 2) {
        __nv_bfloat16* Q2 = (mat == 0) ? (isY ? g_Qy2 : g_Qx2) : (isY ? g_Ky2 : g_Kx2);
#pragma unroll
        for (int mt = 0; mt < 4; mt++) {
            int r = row0 + wm * 64 + mt * 16 + gr;
#pragma unroll
            for (int nt = 0; nt < 4; nt++) {
                int c = col0 + wn * 32 + nt * 8 + kc * 2;
#pragma unroll
                for (int h2 = 0; h2 < 2; h2++) {
                    int rr = r + h2 * 8;
                    float v0 = acc[mt][nt][h2 * 2], v1 = acc[mt][nt][h2 * 2 + 1];
                    __nv_bfloat16 h0 = __float2bfloat16(v0);
                    __nv_bfloat16 h1 = __float2bfloat16(v1);
                    __nv_bfloat162 hi; hi.x = h0; hi.y = h1;
                    __nv_bfloat162 lo;
                    lo.x = __float2bfloat16(v0 - __bfloat162float(h0));
                    lo.y = __float2bfloat16(v1 - __bfloat162float(h1));
                    *(__nv_bfloat162*)(Q2 + (size_t)rr * 512 + c) = hi;
                    *(__nv_bfloat162*)(Q2 + (size_t)rr * 512 + 256 + c) = lo;
                }
            }
        }
    } else {
        float* V = isY ? g_Vy : g_Vx;
#pragma unroll
        for (int mt = 0; mt < 4; mt++) {
            int r = row0 + wm * 64 + mt * 16 + gr;
#pragma unroll
            for (int nt = 0; nt < 4; nt++) {
                int c = col0 + wn * 32 + nt * 8 + kc * 2;
#pragma unroll
                for (int h2 = 0; h2 < 2; h2++) {
                    int rr = r + h2 * 8;
                    *(float2*)(V + (size_t)rr * Dd + c) =
                        make_float2(tf32_rna(acc[mt][nt][h2 * 2]),
                                    tf32_rna(acc[mt][nt][h2 * 2 + 1]));
                }
            }
        }
    }
}

// ---------------- ALL masked score GEMMs + softmax partial stats ----------------
// z in [0,64): scores_x; [64,128): scores_xy (+ mask_xy, no stats);
// [128,136): scores_y. Stats partials: per (row, colTile*4+wn) -> (max, sumexp).
__global__ __launch_bounds__(256, 2) void scores_all(
    float* __restrict__ sx, float* __restrict__ sy,
    float* __restrict__ pxy, float* __restrict__ mxy)
{
    int z = blockIdx.z;
    const __nv_bfloat16 *A, *Bp;
    const unsigned char *mr, *mc;
    float* C;
    float* Mx = nullptr;
    int bz = -1;
    if (z < 64) {
        A = g_Qx2 + (size_t)z * Mm * 512; Bp = g_Kx2 + (size_t)z * Mm * 512;
        mr = g_mx + z * Mm; mc = mr;
        C = sx + (size_t)z * Mm * Mm;
        bz = z;
    } else if (z < 128) {
        int zb = z - 64;
        int n = zb >> 3, s = zb & 7, b = s * 8 + n;
        A = g_Qx2 + (size_t)b * Mm * 512; Bp = g_Ky2 + (size_t)s * Mm * 512;
        mr = g_mx + b * Mm; mc = g_my + s * Mm;
        C = pxy + (size_t)zb * Mm * Mm;
        Mx = mxy + (size_t)zb * Mm * Mm;
    } else {
        int zb = z - 128;
        A = g_Qy2 + (size_t)zb * Mm * 512; Bp = g_Ky2 + (size_t)zb * Mm * 512;
        mr = g_my + zb * Mm; mc = mr;
        C = sy + (size_t)zb * Mm * Mm;
        bz = 64 + zb;
    }
    int row0 = blockIdx.y * 128, col0 = blockIdx.x * 128;

    BF16_SETUP();
    gemm_bf16(A + (size_t)row0 * 512, Bp + (size_t)col0 * 512,
              acc, sb, wm, wn, lane);

#pragma unroll
    for (int mt = 0; mt < 4; mt++) {
        int r = row0 + wm * 64 + mt * 16 + gr;
        bool rm0 = mr[r] != 0, rm1 = mr[r + 8] != 0;
#pragma unroll
        for (int nt = 0; nt < 4; nt++) {
            int c = col0 + wn * 32 + nt * 8 + kc * 2;
            bool c0 = mc[c] != 0, c1 = mc[c + 1] != 0;
            bool m00 = rm0 && c0, m01 = rm0 && c1;
            bool m10 = rm1 && c0, m11 = rm1 && c1;
            float2 v0, v1;
            v0.x = m00 ? acc[mt][nt][0] : NEG_FILL_F;
            v0.y = m01 ? acc[mt][nt][1] : NEG_FILL_F;
            v1.x = m10 ? acc[mt][nt][2] : NEG_FILL_F;
            v1.y = m11 ? acc[mt][nt][3] : NEG_FILL_F;
            *(float2*)(C + (size_t)r * Mm + c) = v0;
            *(float2*)(C + (size_t)(r + 8) * Mm + c) = v1;
            if (Mx) {
                *(float2*)(Mx + (size_t)r * Mm + c) =
                    make_float2(m00 ? 1.f : 0.f, m01 ? 1.f : 0.f);
                *(float2*)(Mx + (size_t)(r + 8) * Mm + c) =
                    make_float2(m10 ? 1.f : 0.f, m11 ? 1.f : 0.f);
            }
        }
    }

    // softmax partial stats for sx / sy tiles
    if (bz >= 0) {
        float2* part = g_part + (size_t)bz * Mm * 16;
        int tcol = blockIdx.x * 4 + wn;
#pragma unroll
        for (int mt = 0; mt < 4; mt++) {
            int rb = row0 + wm * 64 + mt * 16 + gr;
#pragma unroll
            for (int h = 0; h < 2; h++) {
                int r = rb + h * 8;
                bool rmv = mr[r] != 0;
                float lmax = NEG_FILL_F;
#pragma unroll
                for (int nt = 0; nt < 4; nt++) {
                    int c = col0 + wn * 32 + nt * 8 + kc * 2;
                    float a0 = (rmv && mc[c])     ? acc[mt][nt][h * 2]     : NEG_FILL_F;
                    float a1 = (rmv && mc[c + 1]) ? acc[mt][nt][h * 2 + 1] : NEG_FILL_F;
                    lmax = fmaxf(lmax, fmaxf(a0, a1));
                }
                lmax = fmaxf(lmax, __shfl_xor_sync(0xffffffffu, lmax, 1));
                lmax = fmaxf(lmax, __shfl_xor_sync(0xffffffffu, lmax, 2));
                float lsum = 0.f;
#pragma unroll
                for (int nt = 0; nt < 4; nt++) {
                    int c = col0 + wn * 32 + nt * 8 + kc * 2;
                    float a0 = (rmv && mc[c])     ? acc[mt][nt][h * 2]     : NEG_FILL_F;
                    float a1 = (rmv && mc[c + 1]) ? acc[mt][nt][h * 2 + 1] : NEG_FILL_F;
                    lsum += __expf(a0 - lmax) + __expf(a1 - lmax);
                }
                lsum += __shfl_xor_sync(0xffffffffu, lsum, 1);
                lsum += __shfl_xor_sync(0xffffffffu, lsum, 2);
                if (kc == 0)
                    part[(size_t)r * 16 + tcol] = make_float2(lmax, lsum);
            }
        }
    }
}

// ---------------- fused softmax+context: ctx = softmax(S) @ V --------------------
// A operand streamed from RAW scores with on-the-fly exp; stats merged in prologue.
__global__ __launch_bounds__(256, 2) void ctx_all(
    const float* __restrict__ sx, const float* __restrict__ sy,
    float* __restrict__ out_x, float* __restrict__ out_y)
{
    extern __shared__ char smemc[];
    float* As = (float*)smemc;
    float* Bs = As + DEPTH_NN * ASTG32;
    __shared__ float sMax[128], sInv[128];

    int z = blockIdx.z;
    int which = (z >= 64) ? 1 : 0;
    int b = which ? (z - 64) : z;
    const float* S = (which ? sy : sx) + (size_t)b * Mm * Mm;
    const float* V = (which ? g_Vy : g_Vx) + (size_t)b * Mm * Dd;
    float* out = which ? out_y : out_x;
    int row0 = blockIdx.y * 128, col0 = blockIdx.x * 128;
    int bz = which ? 64 + b : b;

    // merge per-row stats
    if (threadIdx.x < 128) {
        int r = row0 + threadIdx.x;
        const float2* part = g_part + ((size_t)bz * Mm + r) * 16;
        float m = NEG_FILL_F;
#pragma unroll
        for (int t = 0; t < 16; t++) m = fmaxf(m, part[t].x);
        float s = 0.f;
#pragma unroll
        for (int t = 0; t < 16; t++) {
            float2 p = part[t];
            s += p.y * __expf(p.x - m);
        }
        sMax[threadIdx.x] = m;
        sInv[threadIdx.x] = 1.0f / s;
    }

    int wid = threadIdx.x >> 5, lane = threadIdx.x & 31;
    int wm = wid >> 2, wn = wid & 3;
    int gr = lane >> 2, kc = lane & 3;
    float acc[4][4][4];
#pragma unroll
    for (int i = 0; i < 4; i++)
#pragma unroll
        for (int j = 0; j < 4; j++)
#pragma unroll
            for (int q = 0; q < 4; q++) acc[i][j][q] = 0.f;

    // A staging config: each thread handles (rowA0, g) and (rowA0+64, g)
    int rowA0 = threadIdx.x >> 2;
    int g = threadIdx.x & 3;
    const float* Ap0 = S + (size_t)(row0 + rowA0) * Mm + g * 4;
    const float* Ap1 = S + (size_t)(row0 + rowA0 + 64) * Mm + g * 4;
    const float* Bp = V + col0;
    uint32_t asb = smem_u32(As), bsb = smem_u32(Bs);
    // scatter STS addresses: permuted pos 4t+g, slot t^(row&3), word g
    uint32_t abase0 = asb + rowA0 * 64 + g * 4;
    uint32_t abase1 = asb + (rowA0 + 64) * 64 + g * 4;
    int sw0 = rowA0 & 3, sw1 = (rowA0 + 64) & 3;

    __syncthreads();   // sMax/sInv ready
    float mx0 = sMax[rowA0], iv0 = sInv[rowA0];
    float mx1 = sMax[rowA0 + 64], iv1 = sInv[rowA0 + 64];

    constexpr int nch = Mm / BK32;   // 32
    float4 cu0 = *(const float4*)(Ap0);
    float4 cu1 = *(const float4*)(Ap1);
#pragma unroll
    for (int s = 0; s < DEPTH_NN - 1; s++)
        issue_stage_nnB(Bp, Dd, s, nch, bsb);

    for (int c = 0; c < nch; c++) {
        float4 nx0, nx1;
        if (c + 1 < nch) {
            nx0 = *(const float4*)(Ap0 + (c + 1) * BK32);
            nx1 = *(const float4*)(Ap1 + (c + 1) * BK32);
        }
        // exp-transform + scatter STS into buffer c%DEPTH_NN
        {
            uint32_t bufo = (uint32_t)((c & (DEPTH_NN - 1)) * (ASTG32 * 4));
            float p0[4] = {cu0.x, cu0.y, cu0.z, cu0.w};
            float p1[4] = {cu1.x, cu1.y, cu1.z, cu1.w};
#pragma unroll
            for (int t = 0; t < 4; t++) {
                float w0 = tf32_rna(__expf(p0[t] - mx0) * iv0);
                float w1 = tf32_rna(__expf(p1[t] - mx1) * iv1);
                sts32(abase0 + bufo + (uint32_t)((t ^ sw0) * 16), w0);
                sts32(abase1 + bufo + (uint32_t)((t ^ sw1) * 16), w1);
            }
        }
        asm volatile("cp.async.wait_group 2;" ::: "memory");
        __syncthreads();
        issue_stage_nnB(Bp, Dd, c + DEPTH_NN - 1, nch, bsb);
        int buf = c & (DEPTH_NN - 1);
        compute_chunk_nn(As + buf * ASTG32, Bs + buf * BSTG_NN, acc, wm, wn, gr, kc);
        cu0 = nx0; cu1 = nx1;
    }

    float* O = out + (size_t)b * Mm * Dd;
#pragma unroll
    for (int mt = 0; mt < 4; mt++) {
        int r = row0 + wm * 64 + mt * 16 + gr;
#pragma unroll
        for (int nt = 0; nt < 4; nt++) {
            int c = col0 + wn * 32 + nt * 8 + kc * 2;
            *(float2*)(O + (size_t)r * Dd + c) =
                make_float2(acc[mt][nt][0], acc[mt][nt][1]);
            *(float2*)(O + (size_t)(r + 8) * Dd + c) =
                make_float2(acc[mt][nt][2], acc[mt][nt][3]);
        }
    }
}

// ---------------- mask normalization + y_len --------------------------------------
__global__ void norm_masks_kernel(const unsigned int* __restrict__ mx_in,
                                  const unsigned int* __restrict__ my_in,
                                  float* __restrict__ ylen_out)
{
    const unsigned int* in = (blockIdx.x == 0) ? mx_in : my_in;
    unsigned char* out = (blockIdx.x == 0) ? g_mx : g_my;
    int n = (blockIdx.x == 0) ? Bb * Mm : BSs * Mm;

    __shared__ int s_flag;
    if (threadIdx.x == 0) s_flag = 0;
    __syncthreads();
    int local = 0;
    for (int i = threadIdx.x; i < n / 4; i += blockDim.x)
        if (in[i] > 1u) local = 1;
    if (local) atomicOr(&s_flag, 1);
    __syncthreads();
    bool byte_packed = (s_flag != 0);

    const unsigned char* inb = (const unsigned char*)in;
    for (int i = threadIdx.x; i < n; i += blockDim.x)
        out[i] = byte_packed ? (inb[i] != 0 ? 1 : 0) : (in[i] != 0u ? 1 : 0);

    if (blockIdx.x == 1) {
        __syncthreads();
        int t = threadIdx.x;
        if (t < 64) {
            int s = t & 7;
            int sum = 0;
            for (int j = 0; j < Mm; j++) sum += g_my[s * Mm + j] ? 1 : 0;
            ylen_out[t] = (float)sum;
        }
    }
}

// ---------------- pxy softmax (in place, raw fp32 output) --------------------------
__global__ __launch_bounds__(256) void softmax_pxy(float* __restrict__ pxy)
{
    size_t row = blockIdx.x;
    float* p = pxy + row * Mm;
    int t = threadIdx.x;

    float v0 = p[t];
    float v1 = p[t + 256];
    float m = fmaxf(v0, v1);
#pragma unroll
    for (int off = 16; off; off >>= 1)
        m = fmaxf(m, __shfl_xor_sync(0xffffffffu, m, off));
    __shared__ float smax[8], ssum[8];
    if ((t & 31) == 0) smax[t >> 5] = m;
    __syncthreads();
    float bm = smax[0];
#pragma unroll
    for (int i = 1; i < 8; i++) bm = fmaxf(bm, smax[i]);

    float e0 = __expf(v0 - bm);
    float e1 = __expf(v1 - bm);
    float s = e0 + e1;
#pragma unroll
    for (int off = 16; off; off >>= 1)
        s += __shfl_xor_sync(0xffffffffu, s, off);
    if ((t & 31) == 0) ssum[t >> 5] = s;
    __syncthreads();
    float tot = 0.f;
#pragma unroll
    for (int i = 0; i < 8; i++) tot += ssum[i];
    float inv = 1.0f / tot;
    p[t] = e0 * inv;
    p[t + 256] = e1 * inv;
}

// ---------------- launch --------------------------------------------------------------
extern "C" void kernel_launch(void* const* d_in, const int* in_sizes, int n_in,
                              void* d_out, int out_size)
{
    const float* x  = (const float*)d_in[0];
    const float* y  = (const float*)d_in[1];
    const unsigned int* mask_x = (const unsigned int*)d_in[2];
    const unsigned int* mask_y = (const unsigned int*)d_in[3];
    const float* Wq = (const float*)d_in[4];
    const float* Wk = (const float*)d_in[5];
    const float* Wv = (const float*)d_in[6];

    float* out = (float*)d_out;
    float* out_ctx_x = out;                    // 64*512*256
    float* out_ctx_y = out + 8388608;          // 8*512*256
    float* out_sx    = out + 9437184;          // 64*512*512
    float* out_sy    = out + 26214400;         // 8*512*512
    float* out_pxy   = out + 28311552;         // 64*512*512
    float* out_mxy   = out + 45088768;         // 64*512*512
    float* out_ylen  = out + 61865984;         // 64

    cudaFuncSetAttribute(proj_kernel, cudaFuncAttributeMaxDynamicSharedMemorySize, DSMEM_BF);
    cudaFuncSetAttribute(scores_all, cudaFuncAttributeMaxDynamicSharedMemorySize, DSMEM_BF);
    cudaFuncSetAttribute(ctx_all, cudaFuncAttributeMaxDynamicSharedMemorySize, DSMEM_NN);

    dim3 blk(256);

    norm_masks_kernel<<<2, 1024>>>(mask_x, mask_y, out_ylen);                // 1
    {
        constexpr size_t TOT = (size_t)Bb * Mm * Dd + (size_t)BSs * Mm * Dd
                             + 3 * (size_t)Dd * Dd;
        split_all<<<(unsigned)((TOT + 255) / 256), 256>>>(x, y, Wq, Wk, Wv);  // 2
    }
    proj_kernel<<<dim3(2, 288, 3), blk, DSMEM_BF>>>();                       // 3
    scores_all<<<dim3(4, 4, 136), blk, DSMEM_BF>>>(out_sx, out_sy,
                                                   out_pxy, out_mxy);        // 4 <- profiled
    ctx_all<<<dim3(2, 4, 72), blk, DSMEM_NN>>>(out_sx, out_sy,
                                               out_ctx_x, out_ctx_y);        // 5
    softmax_pxy<<<Bb * Mm, 256>>>(out_pxy);                                  // 6
}

// round 14
// speedup vs baseline: 2.1389x; 1.0598x over previous
#include <cuda_runtime.h>
#include <cuda_bf16.h>
#include <cstdint>

constexpr int Bb  = 64;
constexpr int BSs = 8;
constexpr int Mm  = 512;
constexpr int Dd  = 256;
constexpr float NEG_FILL_F = -10000000000.0f;

// bf16 fused path: chunk = 32 bf16 k; stage = 4 tiles (Ahi,Alo,Bhi,Blo) x 8KB
constexpr int DEPTH_BF = 3;
constexpr int TSZ     = 8192;
constexpr int BSTAGE  = 4 * TSZ;                       // 32KB per stage
constexpr int DSMEM_BF = DEPTH_BF * BSTAGE;            // 96KB, 2 CTAs/SM
// fp32 NN path (ctx): BK=16 fp32
constexpr int DEPTH_NN = 4;
constexpr int BK32   = 16;
constexpr int BNNP   = 136;
constexpr int ASTG32   = 128 * BK32;                   // floats
constexpr int BSTG_NN  = BK32 * BNNP;                  // floats
constexpr int DSMEM_NN = DEPTH_NN * (ASTG32 + BSTG_NN) * 4;  // 67584 B

// ---------------- scratch ------------------------------------------------------
__device__ __nv_bfloat16 g_x2[(size_t)Bb * Mm * 2 * Dd];   // [hi|lo] width 512
__device__ __nv_bfloat16 g_y2[(size_t)BSs * Mm * 2 * Dd];
__device__ __nv_bfloat16 g_W2[3][(size_t)Dd * 2 * Dd];
__device__ __nv_bfloat16 g_Qx2[(size_t)Bb * Mm * 2 * Dd];
__device__ __nv_bfloat16 g_Kx2[(size_t)Bb * Mm * 2 * Dd];
__device__ __nv_bfloat16 g_Qy2[(size_t)BSs * Mm * 2 * Dd];
__device__ __nv_bfloat16 g_Ky2[(size_t)BSs * Mm * 2 * Dd];
__device__ float g_Vx[(size_t)Bb * Mm * Dd];        // V fp32 tf32-rna
__device__ float g_Vy[(size_t)BSs * Mm * Dd];
// per-(batch,row,tile16) row-max partials. batches: 0..63 x, 64..71 y
__device__ float g_part[(size_t)(Bb + BSs) * Mm * 16];
__device__ unsigned char g_mx[Bb * Mm];
__device__ unsigned char g_my[BSs * Mm];

// ---------------- helpers ------------------------------------------------------
__device__ __forceinline__ float tf32_rna(float a) {
    uint32_t o;
    asm("cvt.rna.tf32.f32 %0, %1;" : "=r"(o) : "f"(a));
    return __uint_as_float(o);
}
__device__ __forceinline__ uint32_t smem_u32(const void* p) {
    uint32_t a;
    asm("{ .reg .u64 t; cvta.to.shared.u64 t, %1; cvt.u32.u64 %0, t; }"
        : "=r"(a) : "l"(p));
    return a;
}
__device__ __forceinline__ void cpa16(uint32_t dst, const void* src) {
    asm volatile("cp.async.cg.shared.global [%0], [%1], 16;"
                 :: "r"(dst), "l"(src) : "memory");
}
__device__ __forceinline__ void sts32(uint32_t addr, float v) {
    asm volatile("st.shared.f32 [%0], %1;" :: "r"(addr), "f"(v) : "memory");
}
__device__ __forceinline__ void ldm_x4(uint32_t* r, uint32_t addr) {
    asm volatile("ldmatrix.sync.aligned.m8n8.x4.shared.b16 {%0,%1,%2,%3}, [%4];"
        : "=r"(r[0]), "=r"(r[1]), "=r"(r[2]), "=r"(r[3]) : "r"(addr));
}
__device__ __forceinline__ void mma_bf16(float* c, const uint32_t* a,
                                         uint32_t b0, uint32_t b1) {
    asm volatile(
        "mma.sync.aligned.m16n8k16.row.col.f32.bf16.bf16.f32 "
        "{%0,%1,%2,%3}, {%4,%5,%6,%7}, {%8,%9}, {%0,%1,%2,%3};"
        : "+f"(c[0]), "+f"(c[1]), "+f"(c[2]), "+f"(c[3])
        : "r"(a[0]), "r"(a[1]), "r"(a[2]), "r"(a[3]), "r"(b0), "r"(b1));
}
__device__ __forceinline__ void mma_tf32(float* c, const uint32_t* a, const uint32_t* b) {
    asm volatile(
        "mma.sync.aligned.m16n8k8.row.col.f32.tf32.tf32.f32 "
        "{%0,%1,%2,%3}, {%4,%5,%6,%7}, {%8,%9}, {%0,%1,%2,%3};"
        : "+f"(c[0]), "+f"(c[1]), "+f"(c[2]), "+f"(c[3])
        : "r"(a[0]), "r"(a[1]), "r"(a[2]), "r"(a[3]), "r"(b[0]), "r"(b[1]));
}

// ============================ fused bf16 NT GEMM path ==========================
__device__ __forceinline__ void issue_stage_f(
    const __nv_bfloat16* __restrict__ A, const __nv_bfloat16* __restrict__ B,
    int c, int nch, uint32_t sb)
{
    if (c < nch) {
        uint32_t sd = sb + (c % DEPTH_BF) * BSTAGE;
        int acol = c * 32;
#pragma unroll
        for (int j = 0; j < 2; j++) {
            int idx = threadIdx.x + 256 * j;
            int row = idx >> 2, slot = idx & 3;
            int g = slot ^ ((row >> 1) & 3);
            uint32_t so = row * 64 + slot * 16;
            const __nv_bfloat16* ap = A + (size_t)row * 512 + acol + g * 8;
            const __nv_bfloat16* bp = B + (size_t)row * 512 + acol + g * 8;
            cpa16(sd + so, ap);                       // A hi
            cpa16(sd + TSZ + so, ap + 256);           // A lo
            cpa16(sd + 2 * TSZ + so, bp);             // B hi
            cpa16(sd + 3 * TSZ + so, bp + 256);       // B lo
        }
    }
    asm volatile("cp.async.commit_group;" ::: "memory");
}

__device__ __forceinline__ void compute_chunk_f(
    uint32_t sd, float (&acc)[4][4][4], int wm, int wn, int lane)
{
    int j = lane >> 3, rin = lane & 7;
    int jk = j >> 1, jo = (j & 1) * 8;
    int rowA = wm * 64 + jo + rin;
    int rowB = wn * 32 + jo + rin;
    int swA = (rowA >> 1) & 3, swB = (rowB >> 1) & 3;
#pragma unroll
    for (int ks = 0; ks < 2; ks++) {
        uint32_t slA = (uint32_t)(((ks * 2 + jk) ^ swA) * 16);
        uint32_t slB = (uint32_t)(((ks * 2 + jk) ^ swB) * 16);
        uint32_t bhi[2][4], blo[2][4];
#pragma unroll
        for (int np = 0; np < 2; np++) {
            ldm_x4(bhi[np], sd + 2 * TSZ + (rowB + np * 16) * 64 + slB);
            ldm_x4(blo[np], sd + 3 * TSZ + (rowB + np * 16) * 64 + slB);
        }
#pragma unroll
        for (int mt = 0; mt < 4; mt++) {
            uint32_t ahi[4], alo[4];
            ldm_x4(ahi, sd + (rowA + mt * 16) * 64 + slA);
            ldm_x4(alo, sd + TSZ + (rowA + mt * 16) * 64 + slA);
#pragma unroll
            for (int nt = 0; nt < 4; nt++) {
                uint32_t b0 = bhi[nt >> 1][nt & 1], b1 = bhi[nt >> 1][(nt & 1) + 2];
                mma_bf16(acc[mt][nt], ahi, b0, b1);
                mma_bf16(acc[mt][nt], alo, b0, b1);
                mma_bf16(acc[mt][nt], ahi,
                         blo[nt >> 1][nt & 1], blo[nt >> 1][(nt & 1) + 2]);
            }
        }
    }
}

__device__ __forceinline__ void gemm_bf16(
    const __nv_bfloat16* __restrict__ A, const __nv_bfloat16* __restrict__ B,
    float (&acc)[4][4][4], uint32_t sb, int wm, int wn, int lane)
{
    constexpr int nch = 8;
#pragma unroll
    for (int s = 0; s < DEPTH_BF - 1; s++)
        issue_stage_f(A, B, s, nch, sb);
    for (int c = 0; c < nch; c++) {
        asm volatile("cp.async.wait_group 1;" ::: "memory");
        __syncthreads();
        issue_stage_f(A, B, c + DEPTH_BF - 1, nch, sb);
        compute_chunk_f(sb + (c % DEPTH_BF) * BSTAGE, acc, wm, wn, lane);
    }
}

#define BF16_SETUP()                                        \
    extern __shared__ char smem[];                          \
    uint32_t sb = smem_u32(smem);                           \
    int wid = threadIdx.x >> 5, lane = threadIdx.x & 31;    \
    int wm = wid >> 2, wn = wid & 3;                        \
    int gr = lane >> 2, kc = lane & 3;                      \
    float acc[4][4][4];                                     \
    _Pragma("unroll") for (int i = 0; i < 4; i++)           \
    _Pragma("unroll") for (int jj = 0; jj < 4; jj++)        \
    _Pragma("unroll") for (int q = 0; q < 4; q++) acc[i][jj][q] = 0.f;

// ============================ fp32 NN path (ctx only) ==========================
__device__ __forceinline__ void issue_stage_nnB(
    const float* __restrict__ B, int ldb, int c, int nch, uint32_t bsb)
{
    if (c < nch) {
        int buf = c & (DEPTH_NN - 1);
        uint32_t bd = bsb + buf * (BSTG_NN * 4);
#pragma unroll
        for (int j = 0; j < 2; j++) {             // B: 16 k-rows x 32 segs
            int idx = threadIdx.x + 256 * j;
            int row = idx >> 5, seg = idx & 31;
            cpa16(bd + (row * BNNP + seg * 4) * 4,
                  B + (size_t)(c * BK32 + row) * ldb + seg * 4);
        }
    }
    asm volatile("cp.async.commit_group;" ::: "memory");
}

__device__ __forceinline__ void compute_chunk_nn(
    const float* __restrict__ As, const float* __restrict__ Bs,
    float (&acc)[4][4][4], int wm, int wn, int gr, int kc)
{
    const int slot4 = (kc ^ (gr & 3)) * 4;
    uint32_t a[2][4][4], b[2][4][2];
#pragma unroll
    for (int mt = 0; mt < 4; mt++) {
        int r0 = wm * 64 + mt * 16 + gr;
        float4 u = *(const float4*)(As + r0 * BK32 + slot4);
        float4 w = *(const float4*)(As + (r0 + 8) * BK32 + slot4);
        a[0][mt][0] = __float_as_uint(u.x); a[0][mt][1] = __float_as_uint(w.x);
        a[0][mt][2] = __float_as_uint(u.y); a[0][mt][3] = __float_as_uint(w.y);
        a[1][mt][0] = __float_as_uint(u.z); a[1][mt][1] = __float_as_uint(w.z);
        a[1][mt][2] = __float_as_uint(u.w); a[1][mt][3] = __float_as_uint(w.w);
    }
#pragma unroll
    for (int k8 = 0; k8 < 2; k8++)
#pragma unroll
        for (int nt = 0; nt < 4; nt++) {
            const float* p = Bs + (k8 * 8 + kc) * BNNP + wn * 32 + nt * 8 + gr;
            b[k8][nt][0] = __float_as_uint(p[0]);
            b[k8][nt][1] = __float_as_uint(p[4 * BNNP]);
        }
#pragma unroll
    for (int k8 = 0; k8 < 2; k8++)
#pragma unroll
        for (int mt = 0; mt < 4; mt++)
#pragma unroll
            for (int nt = 0; nt < 4; nt++)
                mma_tf32(acc[mt][nt], a[k8][mt], b[k8][nt]);
}

// ---------------- fused split: x/y/W -> bf16 [hi | lo] --------------------------
__global__ void split_all(const float* __restrict__ x, const float* __restrict__ y,
                          const float* __restrict__ Wq, const float* __restrict__ Wk,
                          const float* __restrict__ Wv)
{
    constexpr size_t NX = (size_t)Bb * Mm * Dd;
    constexpr size_t NY = (size_t)BSs * Mm * Dd;
    constexpr size_t NW = (size_t)Dd * Dd;
    size_t i = (size_t)blockIdx.x * blockDim.x + threadIdx.x;
    if (i < NX) {
        int r = (int)(i / Dd), c = (int)(i % Dd);
        float v = x[i];
        __nv_bfloat16 h = __float2bfloat16(v);
        g_x2[(size_t)r * 512 + c] = h;
        g_x2[(size_t)r * 512 + 256 + c] = __float2bfloat16(v - __bfloat162float(h));
    } else if (i < NX + NY) {
        size_t e = i - NX;
        int r = (int)(e / Dd), c = (int)(e % Dd);
        float v = y[e];
        __nv_bfloat16 h = __float2bfloat16(v);
        g_y2[(size_t)r * 512 + c] = h;
        g_y2[(size_t)r * 512 + 256 + c] = __float2bfloat16(v - __bfloat162float(h));
    } else if (i < NX + NY + 3 * NW) {
        size_t j = i - NX - NY;
        int w = (int)(j / NW);
        size_t e = j % NW;
        int r = (int)(e / Dd), c = (int)(e % Dd);
        const float* W = (w == 0) ? Wq : (w == 1) ? Wk : Wv;
        float v = W[e];
        __nv_bfloat16 h = __float2bfloat16(v);
        g_W2[w][(size_t)r * 512 + c] = h;
        g_W2[w][(size_t)r * 512 + 256 + c] = __float2bfloat16(v - __bfloat162float(h));
    }
}

// ---------------- projections (fused 3-term bf16), exact grid -------------------
__global__ __launch_bounds__(256, 2) void proj_kernel()
{
    bool isY = blockIdx.y >= 256;
    int mat = blockIdx.z;
    const __nv_bfloat16* A2 = isY ? g_y2 : g_x2;
    const __nv_bfloat16* B2 = g_W2[mat];
    int row0 = (isY ? (blockIdx.y - 256) : blockIdx.y) * 128;
    int col0 = blockIdx.x * 128;

    BF16_SETUP();
    gemm_bf16(A2 + (size_t)row0 * 512, B2 + (size_t)col0 * 512,
              acc, sb, wm, wn, lane);

    if (mat < 2) {
        __nv_bfloat16* Q2 = (mat == 0) ? (isY ? g_Qy2 : g_Qx2) : (isY ? g_Ky2 : g_Kx2);
#pragma unroll
        for (int mt = 0; mt < 4; mt++) {
            int r = row0 + wm * 64 + mt * 16 + gr;
#pragma unroll
            for (int nt = 0; nt < 4; nt++) {
                int c = col0 + wn * 32 + nt * 8 + kc * 2;
#pragma unroll
                for (int h2 = 0; h2 < 2; h2++) {
                    int rr = r + h2 * 8;
                    float v0 = acc[mt][nt][h2 * 2], v1 = acc[mt][nt][h2 * 2 + 1];
                    __nv_bfloat16 h0 = __float2bfloat16(v0);
                    __nv_bfloat16 h1 = __float2bfloat16(v1);
                    __nv_bfloat162 hi; hi.x = h0; hi.y = h1;
                    __nv_bfloat162 lo;
                    lo.x = __float2bfloat16(v0 - __bfloat162float(h0));
                    lo.y = __float2bfloat16(v1 - __bfloat162float(h1));
                    *(__nv_bfloat162*)(Q2 + (size_t)rr * 512 + c) = hi;
                    *(__nv_bfloat162*)(Q2 + (size_t)rr * 512 + 256 + c) = lo;
                }
            }
        }
    } else {
        float* V = isY ? g_Vy : g_Vx;
#pragma unroll
        for (int mt = 0; mt < 4; mt++) {
            int r = row0 + wm * 64 + mt * 16 + gr;
#pragma unroll
            for (int nt = 0; nt < 4; nt++) {
                int c = col0 + wn * 32 + nt * 8 + kc * 2;
#pragma unroll
                for (int h2 = 0; h2 < 2; h2++) {
                    int rr = r + h2 * 8;
                    *(float2*)(V + (size_t)rr * Dd + c) =
                        make_float2(tf32_rna(acc[mt][nt][h2 * 2]),
                                    tf32_rna(acc[mt][nt][h2 * 2 + 1]));
                }
            }
        }
    }
}

// ---------------- ALL masked score GEMMs + row-max partials ---------------------
// z in [0,64): scores_x; [64,128): scores_xy (+ mask_xy, no stats);
// [128,136): scores_y. Max partial per (row, colTile*4+wn), fmax only.
__global__ __launch_bounds__(256, 2) void scores_all(
    float* __restrict__ sx, float* __restrict__ sy,
    float* __restrict__ pxy, float* __restrict__ mxy)
{
    int z = blockIdx.z;
    const __nv_bfloat16 *A, *Bp;
    const unsigned char *mr, *mc;
    float* C;
    float* Mx = nullptr;
    int bz = -1;
    if (z < 64) {
        A = g_Qx2 + (size_t)z * Mm * 512; Bp = g_Kx2 + (size_t)z * Mm * 512;
        mr = g_mx + z * Mm; mc = mr;
        C = sx + (size_t)z * Mm * Mm;
        bz = z;
    } else if (z < 128) {
        int zb = z - 64;
        int n = zb >> 3, s = zb & 7, b = s * 8 + n;
        A = g_Qx2 + (size_t)b * Mm * 512; Bp = g_Ky2 + (size_t)s * Mm * 512;
        mr = g_mx + b * Mm; mc = g_my + s * Mm;
        C = pxy + (size_t)zb * Mm * Mm;
        Mx = mxy + (size_t)zb * Mm * Mm;
    } else {
        int zb = z - 128;
        A = g_Qy2 + (size_t)zb * Mm * 512; Bp = g_Ky2 + (size_t)zb * Mm * 512;
        mr = g_my + zb * Mm; mc = mr;
        C = sy + (size_t)zb * Mm * Mm;
        bz = 64 + zb;
    }
    int row0 = blockIdx.y * 128, col0 = blockIdx.x * 128;

    BF16_SETUP();
    gemm_bf16(A + (size_t)row0 * 512, Bp + (size_t)col0 * 512,
              acc, sb, wm, wn, lane);

#pragma unroll
    for (int mt = 0; mt < 4; mt++) {
        int r = row0 + wm * 64 + mt * 16 + gr;
        bool rm0 = mr[r] != 0, rm1 = mr[r + 8] != 0;
        float rx0 = NEG_FILL_F, rx1 = NEG_FILL_F;   // per-(mt,h) max of masked vals
#pragma unroll
        for (int nt = 0; nt < 4; nt++) {
            int c = col0 + wn * 32 + nt * 8 + kc * 2;
            bool c0 = mc[c] != 0, c1 = mc[c + 1] != 0;
            bool m00 = rm0 && c0, m01 = rm0 && c1;
            bool m10 = rm1 && c0, m11 = rm1 && c1;
            float2 v0, v1;
            v0.x = m00 ? acc[mt][nt][0] : NEG_FILL_F;
            v0.y = m01 ? acc[mt][nt][1] : NEG_FILL_F;
            v1.x = m10 ? acc[mt][nt][2] : NEG_FILL_F;
            v1.y = m11 ? acc[mt][nt][3] : NEG_FILL_F;
            rx0 = fmaxf(rx0, fmaxf(v0.x, v0.y));
            rx1 = fmaxf(rx1, fmaxf(v1.x, v1.y));
            *(float2*)(C + (size_t)r * Mm + c) = v0;
            *(float2*)(C + (size_t)(r + 8) * Mm + c) = v1;
            if (Mx) {
                *(float2*)(Mx + (size_t)r * Mm + c) =
                    make_float2(m00 ? 1.f : 0.f, m01 ? 1.f : 0.f);
                *(float2*)(Mx + (size_t)(r + 8) * Mm + c) =
                    make_float2(m10 ? 1.f : 0.f, m11 ? 1.f : 0.f);
            }
        }
        if (bz >= 0) {
            rx0 = fmaxf(rx0, __shfl_xor_sync(0xffffffffu, rx0, 1));
            rx0 = fmaxf(rx0, __shfl_xor_sync(0xffffffffu, rx0, 2));
            rx1 = fmaxf(rx1, __shfl_xor_sync(0xffffffffu, rx1, 1));
            rx1 = fmaxf(rx1, __shfl_xor_sync(0xffffffffu, rx1, 2));
            if (kc == 0) {
                float* part = g_part + (size_t)bz * Mm * 16;
                int tcol = blockIdx.x * 4 + wn;
                part[(size_t)r * 16 + tcol] = rx0;
                part[(size_t)(r + 8) * 16 + tcol] = rx1;
            }
        }
    }
}

// ---------------- fused softmax+context: ctx = softmax(S) @ V --------------------
// A streamed from RAW scores; exp applied during staging; row sums accumulated in
// fp32 alongside; 1/sum applied post-GEMM (linear).
__global__ __launch_bounds__(256, 2) void ctx_all(
    const float* __restrict__ sx, const float* __restrict__ sy,
    float* __restrict__ out_x, float* __restrict__ out_y)
{
    extern __shared__ char smemc[];
    float* As = (float*)smemc;
    float* Bs = As + DEPTH_NN * ASTG32;
    __shared__ float sMax[128], sInv[128];

    int z = blockIdx.z;
    int which = (z >= 64) ? 1 : 0;
    int b = which ? (z - 64) : z;
    const float* S = (which ? sy : sx) + (size_t)b * Mm * Mm;
    const float* V = (which ? g_Vy : g_Vx) + (size_t)b * Mm * Dd;
    float* out = which ? out_y : out_x;
    int row0 = blockIdx.y * 128, col0 = blockIdx.x * 128;
    int bz = which ? 64 + b : b;

    // merge per-row max partials (fmax only)
    if (threadIdx.x < 128) {
        int r = row0 + threadIdx.x;
        const float* part = g_part + ((size_t)bz * Mm + r) * 16;
        float m = NEG_FILL_F;
#pragma unroll
        for (int t = 0; t < 16; t++) m = fmaxf(m, part[t]);
        sMax[threadIdx.x] = m;
    }

    int wid = threadIdx.x >> 5, lane = threadIdx.x & 31;
    int wm = wid >> 2, wn = wid & 3;
    int gr = lane >> 2, kc = lane & 3;
    float acc[4][4][4];
#pragma unroll
    for (int i = 0; i < 4; i++)
#pragma unroll
        for (int j = 0; j < 4; j++)
#pragma unroll
            for (int q = 0; q < 4; q++) acc[i][j][q] = 0.f;

    // A staging: thread handles rows (rowA0, rowA0+64), 4-float group g
    int rowA0 = threadIdx.x >> 2;
    int g = threadIdx.x & 3;
    const float* Ap0 = S + (size_t)(row0 + rowA0) * Mm + g * 4;
    const float* Ap1 = S + (size_t)(row0 + rowA0 + 64) * Mm + g * 4;
    const float* Bp = V + col0;
    uint32_t asb = smem_u32(As), bsb = smem_u32(Bs);
    uint32_t abase0 = asb + rowA0 * 64 + g * 4;
    uint32_t abase1 = asb + (rowA0 + 64) * 64 + g * 4;
    int sw0 = rowA0 & 3, sw1 = (rowA0 + 64) & 3;

    __syncthreads();   // sMax ready
    float mx0 = sMax[rowA0], mx1 = sMax[rowA0 + 64];
    float sum0 = 0.f, sum1 = 0.f;

    constexpr int nch = Mm / BK32;   // 32
    float4 cu0 = *(const float4*)(Ap0);
    float4 cu1 = *(const float4*)(Ap1);
#pragma unroll
    for (int s = 0; s < DEPTH_NN - 1; s++)
        issue_stage_nnB(Bp, Dd, s, nch, bsb);

    for (int c = 0; c < nch; c++) {
        float4 nx0, nx1;
        if (c + 1 < nch) {
            nx0 = *(const float4*)(Ap0 + (c + 1) * BK32);
            nx1 = *(const float4*)(Ap1 + (c + 1) * BK32);
        }
        {
            uint32_t bufo = (uint32_t)((c & (DEPTH_NN - 1)) * (ASTG32 * 4));
            float p0[4] = {cu0.x, cu0.y, cu0.z, cu0.w};
            float p1[4] = {cu1.x, cu1.y, cu1.z, cu1.w};
#pragma unroll
            for (int t = 0; t < 4; t++) {
                float e0 = __expf(p0[t] - mx0);
                float e1 = __expf(p1[t] - mx1);
                sum0 += e0; sum1 += e1;
                sts32(abase0 + bufo + (uint32_t)((t ^ sw0) * 16), tf32_rna(e0));
                sts32(abase1 + bufo + (uint32_t)((t ^ sw1) * 16), tf32_rna(e1));
            }
        }
        asm volatile("cp.async.wait_group 2;" ::: "memory");
        __syncthreads();
        issue_stage_nnB(Bp, Dd, c + DEPTH_NN - 1, nch, bsb);
        int buf = c & (DEPTH_NN - 1);
        compute_chunk_nn(As + buf * ASTG32, Bs + buf * BSTG_NN, acc, wm, wn, gr, kc);
        cu0 = nx0; cu1 = nx1;
    }

    // quad-reduce row sums, publish inverse
    sum0 += __shfl_xor_sync(0xffffffffu, sum0, 1);
    sum0 += __shfl_xor_sync(0xffffffffu, sum0, 2);
    sum1 += __shfl_xor_sync(0xffffffffu, sum1, 1);
    sum1 += __shfl_xor_sync(0xffffffffu, sum1, 2);
    __syncthreads();   // all compute on As done before reuse of sInv store order
    if (g == 0) {
        sInv[rowA0] = 1.0f / sum0;
        sInv[rowA0 + 64] = 1.0f / sum1;
    }
    __syncthreads();

    float* O = out + (size_t)b * Mm * Dd;
#pragma unroll
    for (int mt = 0; mt < 4; mt++) {
        int rl = wm * 64 + mt * 16 + gr;
        int r = row0 + rl;
        float i0 = sInv[rl], i1 = sInv[rl + 8];
#pragma unroll
        for (int nt = 0; nt < 4; nt++) {
            int c = col0 + wn * 32 + nt * 8 + kc * 2;
            *(float2*)(O + (size_t)r * Dd + c) =
                make_float2(acc[mt][nt][0] * i0, acc[mt][nt][1] * i0);
            *(float2*)(O + (size_t)(r + 8) * Dd + c) =
                make_float2(acc[mt][nt][2] * i1, acc[mt][nt][3] * i1);
        }
    }
}

// ---------------- mask normalization + y_len --------------------------------------
__global__ void norm_masks_kernel(const unsigned int* __restrict__ mx_in,
                                  const unsigned int* __restrict__ my_in,
                                  float* __restrict__ ylen_out)
{
    const unsigned int* in = (blockIdx.x == 0) ? mx_in : my_in;
    unsigned char* out = (blockIdx.x == 0) ? g_mx : g_my;
    int n = (blockIdx.x == 0) ? Bb * Mm : BSs * Mm;

    __shared__ int s_flag;
    if (threadIdx.x == 0) s_flag = 0;
    __syncthreads();
    int local = 0;
    for (int i = threadIdx.x; i < n / 4; i += blockDim.x)
        if (in[i] > 1u) local = 1;
    if (local) atomicOr(&s_flag, 1);
    __syncthreads();
    bool byte_packed = (s_flag != 0);

    const unsigned char* inb = (const unsigned char*)in;
    for (int i = threadIdx.x; i < n; i += blockDim.x)
        out[i] = byte_packed ? (inb[i] != 0 ? 1 : 0) : (in[i] != 0u ? 1 : 0);

    if (blockIdx.x == 1) {
        __syncthreads();
        int t = threadIdx.x;
        if (t < 64) {
            int s = t & 7;
            int sum = 0;
            for (int j = 0; j < Mm; j++) sum += g_my[s * Mm + j] ? 1 : 0;
            ylen_out[t] = (float)sum;
        }
    }
}

// ---------------- pxy softmax (in place, vectorized float4) ------------------------
__global__ __launch_bounds__(128) void softmax_pxy(float* __restrict__ pxy)
{
    size_t row = blockIdx.x;
    float4* p = (float4*)(pxy + row * Mm);
    int t = threadIdx.x;

    float4 v = p[t];
    float m = fmaxf(fmaxf(v.x, v.y), fmaxf(v.z, v.w));
#pragma unroll
    for (int off = 16; off; off >>= 1)
        m = fmaxf(m, __shfl_xor_sync(0xffffffffu, m, off));
    __shared__ float smax[4], ssum[4];
    if ((t & 31) == 0) smax[t >> 5] = m;
    __syncthreads();
    float bm = fmaxf(fmaxf(smax[0], smax[1]), fmaxf(smax[2], smax[3]));

    float4 e;
    e.x = __expf(v.x - bm); e.y = __expf(v.y - bm);
    e.z = __expf(v.z - bm); e.w = __expf(v.w - bm);
    float s = (e.x + e.y) + (e.z + e.w);
#pragma unroll
    for (int off = 16; off; off >>= 1)
        s += __shfl_xor_sync(0xffffffffu, s, off);
    if ((t & 31) == 0) ssum[t >> 5] = s;
    __syncthreads();
    float inv = 1.0f / ((ssum[0] + ssum[1]) + (ssum[2] + ssum[3]));
    e.x *= inv; e.y *= inv; e.z *= inv; e.w *= inv;
    p[t] = e;
}

// ---------------- launch --------------------------------------------------------------
extern "C" void kernel_launch(void* const* d_in, const int* in_sizes, int n_in,
                              void* d_out, int out_size)
{
    const float* x  = (const float*)d_in[0];
    const float* y  = (const float*)d_in[1];
    const unsigned int* mask_x = (const unsigned int*)d_in[2];
    const unsigned int* mask_y = (const unsigned int*)d_in[3];
    const float* Wq = (const float*)d_in[4];
    const float* Wk = (const float*)d_in[5];
    const float* Wv = (const float*)d_in[6];

    float* out = (float*)d_out;
    float* out_ctx_x = out;                    // 64*512*256
    float* out_ctx_y = out + 8388608;          // 8*512*256
    float* out_sx    = out + 9437184;          // 64*512*512
    float* out_sy    = out + 26214400;         // 8*512*512
    float* out_pxy   = out + 28311552;         // 64*512*512
    float* out_mxy   = out + 45088768;         // 64*512*512
    float* out_ylen  = out + 61865984;         // 64

    cudaFuncSetAttribute(proj_kernel, cudaFuncAttributeMaxDynamicSharedMemorySize, DSMEM_BF);
    cudaFuncSetAttribute(scores_all, cudaFuncAttributeMaxDynamicSharedMemorySize, DSMEM_BF);
    cudaFuncSetAttribute(ctx_all, cudaFuncAttributeMaxDynamicSharedMemorySize, DSMEM_NN);

    dim3 blk(256);

    norm_masks_kernel<<<2, 1024>>>(mask_x, mask_y, out_ylen);                // 1
    {
        constexpr size_t TOT = (size_t)Bb * Mm * Dd + (size_t)BSs * Mm * Dd
                             + 3 * (size_t)Dd * Dd;
        split_all<<<(unsigned)((TOT + 255) / 256), 256>>>(x, y, Wq, Wk, Wv);  // 2
    }
    proj_kernel<<<dim3(2, 288, 3), blk, DSMEM_BF>>>();                       // 3
    scores_all<<<dim3(4, 4, 136), blk, DSMEM_BF>>>(out_sx, out_sy,
                                                   out_pxy, out_mxy);        // 4 <- profiled
    ctx_all<<<dim3(2, 4, 72), blk, DSMEM_NN>>>(out_sx, out_sy,
                                               out_ctx_x, out_ctx_y);        // 5
    softmax_pxy<<<Bb * Mm, 128>>>(out_pxy);                                  // 6
}